// round 1
// baseline (speedup 1.0000x reference)
#include <cuda_runtime.h>
#include <math.h>

// Problem constants
#define BSZ 2
#define T   2048
#define C   2048
#define NH  16
#define DH  128
#define MROWS (BSZ * T)      // 4096
#define KDIM  C              // 2048
#define NDIM  C              // 2048

// Scratch: q,k,v,attn_out in [B, N, T, D] layout (32 MB each)
__device__ float g_q[BSZ * NH * T * DH];
__device__ float g_k[BSZ * NH * T * DH];
__device__ float g_v[BSZ * NH * T * DH];
__device__ float g_o[BSZ * NH * T * DH];

// ---------------------------------------------------------------------------
// SGEMM: out[M,N] = A[M,K] @ W[K,N] + bias[N]
//   GATHER_A:   A is read from heads layout [B,N,T,D] (for the O projection)
//   SCATTER_OUT:out is written to heads layout [B,N,T,D] (for Q/K/V projections)
// Fixed sizes: M=4096, K=2048, N=2048. BM=BN=128, BK=8, 256 threads, 8x8/thread.
// ---------------------------------------------------------------------------
template <bool GATHER_A, bool SCATTER_OUT>
__global__ __launch_bounds__(256) void sgemm_kernel(
    const float* __restrict__ A, const float* __restrict__ W,
    const float* __restrict__ bias, float* __restrict__ out)
{
    __shared__ float As[8][128];   // transposed: As[k][m]
    __shared__ float Bs[8][128];

    const int tid = threadIdx.x;
    const int tx  = tid & 15;      // 0..15 (n dimension)
    const int ty  = tid >> 4;      // 0..15 (m dimension)

    const int m_base = blockIdx.y * 128;
    const int n_base = blockIdx.x * 128;

    // global load indices
    const int a_row  = tid >> 1;         // 0..127
    const int a_col4 = (tid & 1) * 4;    // 0 or 4
    const int b_row  = tid >> 5;         // 0..7
    const int b_col4 = (tid & 31) * 4;   // 0..124

    float acc[8][8];
#pragma unroll
    for (int i = 0; i < 8; i++)
#pragma unroll
        for (int j = 0; j < 8; j++) acc[i][j] = 0.0f;

    for (int k0 = 0; k0 < KDIM; k0 += 8) {
        // stage loads in registers
        float4 a4;
        if (GATHER_A) {
            const int m = m_base + a_row;
            const int b = m >> 11;           // m / 2048
            const int t = m & 2047;
            const int k = k0 + a_col4;
            const int h = k >> 7;            // k / 128
            const int d = k & 127;
            a4 = *(const float4*)&A[(((size_t)b * NH + h) * T + t) * DH + d];
        } else {
            a4 = *(const float4*)&A[(size_t)(m_base + a_row) * KDIM + k0 + a_col4];
        }
        const float4 b4 = *(const float4*)&W[(size_t)(k0 + b_row) * NDIM + n_base + b_col4];

        __syncthreads();   // prior compute done before overwriting smem
        As[a_col4 + 0][a_row] = a4.x;
        As[a_col4 + 1][a_row] = a4.y;
        As[a_col4 + 2][a_row] = a4.z;
        As[a_col4 + 3][a_row] = a4.w;
        *(float4*)&Bs[b_row][b_col4] = b4;
        __syncthreads();

#pragma unroll
        for (int kk = 0; kk < 8; kk++) {
            float af[8], bf[8];
            *(float4*)&af[0] = *(const float4*)&As[kk][ty * 8];
            *(float4*)&af[4] = *(const float4*)&As[kk][ty * 8 + 4];
            *(float4*)&bf[0] = *(const float4*)&Bs[kk][tx * 8];
            *(float4*)&bf[4] = *(const float4*)&Bs[kk][tx * 8 + 4];
#pragma unroll
            for (int i = 0; i < 8; i++)
#pragma unroll
                for (int j = 0; j < 8; j++)
                    acc[i][j] += af[i] * bf[j];
        }
    }

    // epilogue
#pragma unroll
    for (int i = 0; i < 8; i++) {
        const int m = m_base + ty * 8 + i;
#pragma unroll
        for (int j = 0; j < 8; j += 4) {
            const int n = n_base + tx * 8 + j;
            float4 r;
            r.x = acc[i][j + 0] + bias[n + 0];
            r.y = acc[i][j + 1] + bias[n + 1];
            r.z = acc[i][j + 2] + bias[n + 2];
            r.w = acc[i][j + 3] + bias[n + 3];
            if (SCATTER_OUT) {
                const int b = m >> 11, t = m & 2047;
                const int h = n >> 7, d = n & 127;
                *(float4*)&out[(((size_t)b * NH + h) * T + t) * DH + d] = r;
            } else {
                *(float4*)&out[(size_t)m * NDIM + n] = r;
            }
        }
    }
}

// ---------------------------------------------------------------------------
// Flash attention (causal), per-head. BQ=BKV=64, D=128, 256 threads.
// Dynamic smem layout (floats):
//   Qs[64][132] Ks[64][132] Vs[64][132] Ps[64][68] red[64][17]
//   row_m[64] row_l[64] row_scale[64]
// ---------------------------------------------------------------------------
#define BQ  64
#define BKV 64
#define PADW (DH + 4)       // 132
#define PPAD (BKV + 4)      // 68

#define QS_OFF   0
#define KS_OFF   (QS_OFF + BQ * PADW)
#define VS_OFF   (KS_OFF + BKV * PADW)
#define PS_OFF   (VS_OFF + BKV * PADW)
#define RED_OFF  (PS_OFF + BQ * PPAD)
#define RM_OFF   (RED_OFF + BQ * 17)
#define RL_OFF   (RM_OFF + BQ)
#define RS_OFF   (RL_OFF + BQ)
#define FLASH_SMEM_FLOATS (RS_OFF + BQ)
#define FLASH_SMEM_BYTES  (FLASH_SMEM_FLOATS * 4)   // 123904

__global__ __launch_bounds__(256) void flash_kernel(
    const float* __restrict__ gq, const float* __restrict__ gk,
    const float* __restrict__ gv, float* __restrict__ gout)
{
    extern __shared__ float sm[];
    float (*Qs)[PADW] = (float (*)[PADW])(sm + QS_OFF);
    float (*Ks)[PADW] = (float (*)[PADW])(sm + KS_OFF);
    float (*Vs)[PADW] = (float (*)[PADW])(sm + VS_OFF);
    float (*Ps)[PPAD] = (float (*)[PPAD])(sm + PS_OFF);
    float (*red)[17]  = (float (*)[17])(sm + RED_OFF);
    float* row_m = sm + RM_OFF;
    float* row_l = sm + RL_OFF;
    float* row_s = sm + RS_OFF;

    const int tid = threadIdx.x;
    const int tx  = tid & 15;   // column group
    const int ty  = tid >> 4;   // row group
    const int r0  = ty * 4;     // 4 S-rows per thread
    const int c0  = tx * 4;     // 4 S-cols per thread
    const int cn0 = tx * 8;     // 8 O-cols per thread

    const int qt = blockIdx.x;            // query tile
    const int h  = blockIdx.y;
    const int b  = blockIdx.z;
    const int q0 = qt * BQ;

    const size_t head_off = ((size_t)b * NH + h) * T * DH;
    const float* qbase = gq + head_off;
    const float* kbase = gk + head_off;
    const float* vbase = gv + head_off;

    const float NEG_INF = __int_as_float(0xff800000);
    const float scale   = 0.08838834764831845f;   // 1/sqrt(128)

    // init row state + load Q tile
    if (tid < BQ) { row_m[tid] = NEG_INF; row_l[tid] = 0.0f; }
    for (int i = tid; i < BQ * (DH / 4); i += 256) {
        const int r  = i >> 5;          // DH/4 = 32
        const int c4 = (i & 31) * 4;
        *(float4*)&Qs[r][c4] = *(const float4*)&qbase[(size_t)(q0 + r) * DH + c4];
    }

    float o[4][8];
#pragma unroll
    for (int i = 0; i < 4; i++)
#pragma unroll
        for (int j = 0; j < 8; j++) o[i][j] = 0.0f;

    for (int kt = 0; kt <= qt; kt++) {
        const int kv0 = kt * BKV;
        const bool diag = (kt == qt);

        __syncthreads();   // prior tile done with Ks/Vs/Ps/red
        for (int i = tid; i < BKV * (DH / 4); i += 256) {
            const int r  = i >> 5;
            const int c4 = (i & 31) * 4;
            *(float4*)&Ks[r][c4] = *(const float4*)&kbase[(size_t)(kv0 + r) * DH + c4];
            *(float4*)&Vs[r][c4] = *(const float4*)&vbase[(size_t)(kv0 + r) * DH + c4];
        }
        __syncthreads();

        // S = Q K^T (4x4 per thread)
        float s[4][4];
#pragma unroll
        for (int i = 0; i < 4; i++)
#pragma unroll
            for (int j = 0; j < 4; j++) s[i][j] = 0.0f;

        for (int d = 0; d < DH; d += 4) {
            float4 qv[4], kv[4];
#pragma unroll
            for (int i = 0; i < 4; i++) qv[i] = *(const float4*)&Qs[r0 + i][d];
#pragma unroll
            for (int j = 0; j < 4; j++) kv[j] = *(const float4*)&Ks[c0 + j][d];
#pragma unroll
            for (int i = 0; i < 4; i++)
#pragma unroll
                for (int j = 0; j < 4; j++)
                    s[i][j] += qv[i].x * kv[j].x + qv[i].y * kv[j].y +
                               qv[i].z * kv[j].z + qv[i].w * kv[j].w;
        }

        // scale + causal mask, per-thread row maxima
        float lm[4];
#pragma unroll
        for (int i = 0; i < 4; i++) {
            lm[i] = NEG_INF;
#pragma unroll
            for (int j = 0; j < 4; j++) {
                float val = s[i][j] * scale;
                if (diag && (kv0 + c0 + j > q0 + r0 + i)) val = NEG_INF;
                s[i][j] = val;
                lm[i] = fmaxf(lm[i], val);
            }
            red[r0 + i][tx] = lm[i];
        }
        __syncthreads();

        if (tid < BQ) {
            float mt = red[tid][0];
#pragma unroll
            for (int t2 = 1; t2 < 16; t2++) mt = fmaxf(mt, red[tid][t2]);
            const float mo = row_m[tid];
            const float mn = fmaxf(mo, mt);
            row_m[tid] = mn;
            const float sc = __expf(mo - mn);   // exp(-inf)=0 on first tile
            row_s[tid] = sc;
            row_l[tid] *= sc;
        }
        __syncthreads();

        // P = exp(S - m_new), partial row sums, rescale O
#pragma unroll
        for (int i = 0; i < 4; i++) {
            const float mn = row_m[r0 + i];
            float ls = 0.0f;
#pragma unroll
            for (int j = 0; j < 4; j++) {
                const float p = __expf(s[i][j] - mn);
                Ps[r0 + i][c0 + j] = p;
                ls += p;
            }
            red[r0 + i][tx] = ls;
            const float sc = row_s[r0 + i];
#pragma unroll
            for (int j = 0; j < 8; j++) o[i][j] *= sc;
        }
        __syncthreads();

        if (tid < BQ) {
            float su = red[tid][0];
#pragma unroll
            for (int t2 = 1; t2 < 16; t2++) su += red[tid][t2];
            row_l[tid] += su;
        }

        // O += P V
        for (int kk = 0; kk < BKV; kk++) {
            const float4 v0 = *(const float4*)&Vs[kk][cn0];
            const float4 v1 = *(const float4*)&Vs[kk][cn0 + 4];
#pragma unroll
            for (int i = 0; i < 4; i++) {
                const float p = Ps[r0 + i][kk];
                o[i][0] += p * v0.x; o[i][1] += p * v0.y;
                o[i][2] += p * v0.z; o[i][3] += p * v0.w;
                o[i][4] += p * v1.x; o[i][5] += p * v1.y;
                o[i][6] += p * v1.z; o[i][7] += p * v1.w;
            }
        }
    }

    __syncthreads();   // row_l final
#pragma unroll
    for (int i = 0; i < 4; i++) {
        const float inv = 1.0f / row_l[r0 + i];
        float4 w0, w1;
        w0.x = o[i][0] * inv; w0.y = o[i][1] * inv;
        w0.z = o[i][2] * inv; w0.w = o[i][3] * inv;
        w1.x = o[i][4] * inv; w1.y = o[i][5] * inv;
        w1.z = o[i][6] * inv; w1.w = o[i][7] * inv;
        float* dst = gout + head_off + (size_t)(q0 + r0 + i) * DH + cn0;
        *(float4*)&dst[0] = w0;
        *(float4*)&dst[4] = w1;
    }
}

// ---------------------------------------------------------------------------
extern "C" void kernel_launch(void* const* d_in, const int* in_sizes, int n_in,
                              void* d_out, int out_size)
{
    const float* src = (const float*)d_in[0];
    const float* Wq  = (const float*)d_in[1];
    const float* bq  = (const float*)d_in[2];
    const float* Wk  = (const float*)d_in[3];
    const float* bk  = (const float*)d_in[4];
    const float* Wv  = (const float*)d_in[5];
    const float* bv  = (const float*)d_in[6];
    const float* Wo  = (const float*)d_in[7];
    const float* bo  = (const float*)d_in[8];
    float* out = (float*)d_out;

    float *q, *k, *v, *o;
    cudaGetSymbolAddress((void**)&q, g_q);
    cudaGetSymbolAddress((void**)&k, g_k);
    cudaGetSymbolAddress((void**)&v, g_v);
    cudaGetSymbolAddress((void**)&o, g_o);

    cudaFuncSetAttribute(flash_kernel,
                         cudaFuncAttributeMaxDynamicSharedMemorySize,
                         FLASH_SMEM_BYTES);

    const dim3 gemm_grid(NDIM / 128, MROWS / 128);   // (16, 32)
    const dim3 gemm_blk(256);

    sgemm_kernel<false, true><<<gemm_grid, gemm_blk>>>(src, Wq, bq, q);
    sgemm_kernel<false, true><<<gemm_grid, gemm_blk>>>(src, Wk, bk, k);
    sgemm_kernel<false, true><<<gemm_grid, gemm_blk>>>(src, Wv, bv, v);

    flash_kernel<<<dim3(T / BQ, NH, BSZ), 256, FLASH_SMEM_BYTES>>>(q, k, v, o);

    sgemm_kernel<true, false><<<gemm_grid, gemm_blk>>>(o, Wo, bo, out);
}

// round 2
// speedup vs baseline: 1.0010x; 1.0010x over previous
#include <cuda_runtime.h>
#include <math.h>

// Problem constants
#define BSZ 2
#define T   2048
#define C   2048
#define NH  16
#define DH  128
#define MROWS (BSZ * T)      // 4096
#define KDIM  C              // 2048
#define NDIM  C              // 2048

// Scratch: q,k,v,attn_out in [B, N, T, D] layout (32 MB each)
__device__ float g_q[BSZ * NH * T * DH];
__device__ float g_k[BSZ * NH * T * DH];
__device__ float g_v[BSZ * NH * T * DH];
__device__ float g_o[BSZ * NH * T * DH];

// ---------------------------------------------------------------------------
// SGEMM: out[M,N] = A[M,K] @ W[K,N] + bias[N]
//   GATHER_A:   A is read from heads layout [B,N,T,D] (for the O projection)
//   SCATTER_OUT:out is written to heads layout [B,N,T,D] (for Q/K/V projections)
// Fixed sizes: M=4096, K=2048, N=2048. BM=BN=128, BK=8, 256 threads, 8x8/thread.
// ---------------------------------------------------------------------------
template <bool GATHER_A, bool SCATTER_OUT>
__global__ __launch_bounds__(256) void sgemm_kernel(
    const float* __restrict__ A, const float* __restrict__ W,
    const float* __restrict__ bias, float* __restrict__ out)
{
    __shared__ float As[8][128];   // transposed: As[k][m]
    __shared__ float Bs[8][128];

    const int tid = threadIdx.x;
    const int tx  = tid & 15;      // 0..15 (n dimension)
    const int ty  = tid >> 4;      // 0..15 (m dimension)

    const int m_base = blockIdx.y * 128;
    const int n_base = blockIdx.x * 128;

    // global load indices
    const int a_row  = tid >> 1;         // 0..127
    const int a_col4 = (tid & 1) * 4;    // 0 or 4
    const int b_row  = tid >> 5;         // 0..7
    const int b_col4 = (tid & 31) * 4;   // 0..124

    float acc[8][8];
#pragma unroll
    for (int i = 0; i < 8; i++)
#pragma unroll
        for (int j = 0; j < 8; j++) acc[i][j] = 0.0f;

    for (int k0 = 0; k0 < KDIM; k0 += 8) {
        // stage loads in registers
        float4 a4;
        if (GATHER_A) {
            const int m = m_base + a_row;
            const int b = m >> 11;           // m / 2048
            const int t = m & 2047;
            const int k = k0 + a_col4;
            const int h = k >> 7;            // k / 128
            const int d = k & 127;
            a4 = *(const float4*)&A[(((size_t)b * NH + h) * T + t) * DH + d];
        } else {
            a4 = *(const float4*)&A[(size_t)(m_base + a_row) * KDIM + k0 + a_col4];
        }
        const float4 b4 = *(const float4*)&W[(size_t)(k0 + b_row) * NDIM + n_base + b_col4];

        __syncthreads();   // prior compute done before overwriting smem
        As[a_col4 + 0][a_row] = a4.x;
        As[a_col4 + 1][a_row] = a4.y;
        As[a_col4 + 2][a_row] = a4.z;
        As[a_col4 + 3][a_row] = a4.w;
        *(float4*)&Bs[b_row][b_col4] = b4;
        __syncthreads();

#pragma unroll
        for (int kk = 0; kk < 8; kk++) {
            float af[8], bf[8];
            *(float4*)&af[0] = *(const float4*)&As[kk][ty * 8];
            *(float4*)&af[4] = *(const float4*)&As[kk][ty * 8 + 4];
            *(float4*)&bf[0] = *(const float4*)&Bs[kk][tx * 8];
            *(float4*)&bf[4] = *(const float4*)&Bs[kk][tx * 8 + 4];
#pragma unroll
            for (int i = 0; i < 8; i++)
#pragma unroll
                for (int j = 0; j < 8; j++)
                    acc[i][j] += af[i] * bf[j];
        }
    }

    // epilogue
#pragma unroll
    for (int i = 0; i < 8; i++) {
        const int m = m_base + ty * 8 + i;
#pragma unroll
        for (int j = 0; j < 8; j += 4) {
            const int n = n_base + tx * 8 + j;
            float4 r;
            r.x = acc[i][j + 0] + bias[n + 0];
            r.y = acc[i][j + 1] + bias[n + 1];
            r.z = acc[i][j + 2] + bias[n + 2];
            r.w = acc[i][j + 3] + bias[n + 3];
            if (SCATTER_OUT) {
                const int b = m >> 11, t = m & 2047;
                const int h = n >> 7, d = n & 127;
                *(float4*)&out[(((size_t)b * NH + h) * T + t) * DH + d] = r;
            } else {
                *(float4*)&out[(size_t)m * NDIM + n] = r;
            }
        }
    }
}

// ---------------------------------------------------------------------------
// Flash attention (causal), per-head. BQ=BKV=64, D=128, 256 threads.
// Dynamic smem layout (floats):
//   Qs[64][132] Ks[64][132] Vs[64][132] Ps[64][68] red[64][17]
//   row_m[64] row_l[64] row_scale[64]
// ---------------------------------------------------------------------------
#define BQ  64
#define BKV 64
#define PADW (DH + 4)       // 132
#define PPAD (BKV + 4)      // 68

#define QS_OFF   0
#define KS_OFF   (QS_OFF + BQ * PADW)
#define VS_OFF   (KS_OFF + BKV * PADW)
#define PS_OFF   (VS_OFF + BKV * PADW)
#define RED_OFF  (PS_OFF + BQ * PPAD)
#define RM_OFF   (RED_OFF + BQ * 17)
#define RL_OFF   (RM_OFF + BQ)
#define RS_OFF   (RL_OFF + BQ)
#define FLASH_SMEM_FLOATS (RS_OFF + BQ)
#define FLASH_SMEM_BYTES  (FLASH_SMEM_FLOATS * 4)   // 123904

__global__ __launch_bounds__(256) void flash_kernel(
    const float* __restrict__ gq, const float* __restrict__ gk,
    const float* __restrict__ gv, float* __restrict__ gout)
{
    extern __shared__ float sm[];
    float (*Qs)[PADW] = (float (*)[PADW])(sm + QS_OFF);
    float (*Ks)[PADW] = (float (*)[PADW])(sm + KS_OFF);
    float (*Vs)[PADW] = (float (*)[PADW])(sm + VS_OFF);
    float (*Ps)[PPAD] = (float (*)[PPAD])(sm + PS_OFF);
    float (*red)[17]  = (float (*)[17])(sm + RED_OFF);
    float* row_m = sm + RM_OFF;
    float* row_l = sm + RL_OFF;
    float* row_s = sm + RS_OFF;

    const int tid = threadIdx.x;
    const int tx  = tid & 15;   // column group
    const int ty  = tid >> 4;   // row group
    const int r0  = ty * 4;     // 4 S-rows per thread
    const int c0  = tx * 4;     // 4 S-cols per thread
    const int cn0 = tx * 8;     // 8 O-cols per thread

    const int qt = blockIdx.x;            // query tile
    const int h  = blockIdx.y;
    const int b  = blockIdx.z;
    const int q0 = qt * BQ;

    const size_t head_off = ((size_t)b * NH + h) * T * DH;
    const float* qbase = gq + head_off;
    const float* kbase = gk + head_off;
    const float* vbase = gv + head_off;

    const float NEG_INF = __int_as_float(0xff800000);
    const float scale   = 0.08838834764831845f;   // 1/sqrt(128)

    // init row state + load Q tile
    if (tid < BQ) { row_m[tid] = NEG_INF; row_l[tid] = 0.0f; }
    for (int i = tid; i < BQ * (DH / 4); i += 256) {
        const int r  = i >> 5;          // DH/4 = 32
        const int c4 = (i & 31) * 4;
        *(float4*)&Qs[r][c4] = *(const float4*)&qbase[(size_t)(q0 + r) * DH + c4];
    }

    float o[4][8];
#pragma unroll
    for (int i = 0; i < 4; i++)
#pragma unroll
        for (int j = 0; j < 8; j++) o[i][j] = 0.0f;

    for (int kt = 0; kt <= qt; kt++) {
        const int kv0 = kt * BKV;
        const bool diag = (kt == qt);

        __syncthreads();   // prior tile done with Ks/Vs/Ps/red
        for (int i = tid; i < BKV * (DH / 4); i += 256) {
            const int r  = i >> 5;
            const int c4 = (i & 31) * 4;
            *(float4*)&Ks[r][c4] = *(const float4*)&kbase[(size_t)(kv0 + r) * DH + c4];
            *(float4*)&Vs[r][c4] = *(const float4*)&vbase[(size_t)(kv0 + r) * DH + c4];
        }
        __syncthreads();

        // S = Q K^T (4x4 per thread)
        float s[4][4];
#pragma unroll
        for (int i = 0; i < 4; i++)
#pragma unroll
            for (int j = 0; j < 4; j++) s[i][j] = 0.0f;

        for (int d = 0; d < DH; d += 4) {
            float4 qv[4], kv[4];
#pragma unroll
            for (int i = 0; i < 4; i++) qv[i] = *(const float4*)&Qs[r0 + i][d];
#pragma unroll
            for (int j = 0; j < 4; j++) kv[j] = *(const float4*)&Ks[c0 + j][d];
#pragma unroll
            for (int i = 0; i < 4; i++)
#pragma unroll
                for (int j = 0; j < 4; j++)
                    s[i][j] += qv[i].x * kv[j].x + qv[i].y * kv[j].y +
                               qv[i].z * kv[j].z + qv[i].w * kv[j].w;
        }

        // scale + causal mask, per-thread row maxima
        float lm[4];
#pragma unroll
        for (int i = 0; i < 4; i++) {
            lm[i] = NEG_INF;
#pragma unroll
            for (int j = 0; j < 4; j++) {
                float val = s[i][j] * scale;
                if (diag && (kv0 + c0 + j > q0 + r0 + i)) val = NEG_INF;
                s[i][j] = val;
                lm[i] = fmaxf(lm[i], val);
            }
            red[r0 + i][tx] = lm[i];
        }
        __syncthreads();

        if (tid < BQ) {
            float mt = red[tid][0];
#pragma unroll
            for (int t2 = 1; t2 < 16; t2++) mt = fmaxf(mt, red[tid][t2]);
            const float mo = row_m[tid];
            const float mn = fmaxf(mo, mt);
            row_m[tid] = mn;
            const float sc = __expf(mo - mn);   // exp(-inf)=0 on first tile
            row_s[tid] = sc;
            row_l[tid] *= sc;
        }
        __syncthreads();

        // P = exp(S - m_new), partial row sums, rescale O
#pragma unroll
        for (int i = 0; i < 4; i++) {
            const float mn = row_m[r0 + i];
            float ls = 0.0f;
#pragma unroll
            for (int j = 0; j < 4; j++) {
                const float p = __expf(s[i][j] - mn);
                Ps[r0 + i][c0 + j] = p;
                ls += p;
            }
            red[r0 + i][tx] = ls;
            const float sc = row_s[r0 + i];
#pragma unroll
            for (int j = 0; j < 8; j++) o[i][j] *= sc;
        }
        __syncthreads();

        if (tid < BQ) {
            float su = red[tid][0];
#pragma unroll
            for (int t2 = 1; t2 < 16; t2++) su += red[tid][t2];
            row_l[tid] += su;
        }

        // O += P V
        for (int kk = 0; kk < BKV; kk++) {
            const float4 v0 = *(const float4*)&Vs[kk][cn0];
            const float4 v1 = *(const float4*)&Vs[kk][cn0 + 4];
#pragma unroll
            for (int i = 0; i < 4; i++) {
                const float p = Ps[r0 + i][kk];
                o[i][0] += p * v0.x; o[i][1] += p * v0.y;
                o[i][2] += p * v0.z; o[i][3] += p * v0.w;
                o[i][4] += p * v1.x; o[i][5] += p * v1.y;
                o[i][6] += p * v1.z; o[i][7] += p * v1.w;
            }
        }
    }

    __syncthreads();   // row_l final
#pragma unroll
    for (int i = 0; i < 4; i++) {
        const float inv = 1.0f / row_l[r0 + i];
        float4 w0, w1;
        w0.x = o[i][0] * inv; w0.y = o[i][1] * inv;
        w0.z = o[i][2] * inv; w0.w = o[i][3] * inv;
        w1.x = o[i][4] * inv; w1.y = o[i][5] * inv;
        w1.z = o[i][6] * inv; w1.w = o[i][7] * inv;
        float* dst = gout + head_off + (size_t)(q0 + r0 + i) * DH + cn0;
        *(float4*)&dst[0] = w0;
        *(float4*)&dst[4] = w1;
    }
}

// ---------------------------------------------------------------------------
extern "C" void kernel_launch(void* const* d_in, const int* in_sizes, int n_in,
                              void* d_out, int out_size)
{
    const float* src = (const float*)d_in[0];
    const float* Wq  = (const float*)d_in[1];
    const float* bq  = (const float*)d_in[2];
    const float* Wk  = (const float*)d_in[3];
    const float* bk  = (const float*)d_in[4];
    const float* Wv  = (const float*)d_in[5];
    const float* bv  = (const float*)d_in[6];
    const float* Wo  = (const float*)d_in[7];
    const float* bo  = (const float*)d_in[8];
    float* out = (float*)d_out;

    float *q, *k, *v, *o;
    cudaGetSymbolAddress((void**)&q, g_q);
    cudaGetSymbolAddress((void**)&k, g_k);
    cudaGetSymbolAddress((void**)&v, g_v);
    cudaGetSymbolAddress((void**)&o, g_o);

    cudaFuncSetAttribute(flash_kernel,
                         cudaFuncAttributeMaxDynamicSharedMemorySize,
                         FLASH_SMEM_BYTES);

    const dim3 gemm_grid(NDIM / 128, MROWS / 128);   // (16, 32)
    const dim3 gemm_blk(256);

    sgemm_kernel<false, true><<<gemm_grid, gemm_blk>>>(src, Wq, bq, q);
    sgemm_kernel<false, true><<<gemm_grid, gemm_blk>>>(src, Wk, bk, k);
    sgemm_kernel<false, true><<<gemm_grid, gemm_blk>>>(src, Wv, bv, v);

    flash_kernel<<<dim3(T / BQ, NH, BSZ), 256, FLASH_SMEM_BYTES>>>(q, k, v, o);

    sgemm_kernel<true, false><<<gemm_grid, gemm_blk>>>(o, Wo, bo, out);
}

// round 3
// speedup vs baseline: 1.0017x; 1.0007x over previous
#include <cuda_runtime.h>
#include <math.h>

// Problem constants
#define BSZ 2
#define T   2048
#define C   2048
#define NH  16
#define DH  128
#define MROWS (BSZ * T)      // 4096
#define KDIM  C              // 2048
#define NDIM  C              // 2048

// Scratch: q,k,v,attn_out in [B, N, T, D] layout (32 MB each)
__device__ float g_q[BSZ * NH * T * DH];
__device__ float g_k[BSZ * NH * T * DH];
__device__ float g_v[BSZ * NH * T * DH];
__device__ float g_o[BSZ * NH * T * DH];

// ---------------------------------------------------------------------------
// SGEMM: out[M,N] = A[M,K] @ W[K,N] + bias[N]
//   GATHER_A:   A is read from heads layout [B,N,T,D] (for the O projection)
//   SCATTER_OUT:out is written to heads layout [B,N,T,D] (for Q/K/V projections)
// Fixed sizes: M=4096, K=2048, N=2048. BM=BN=128, BK=8, 256 threads, 8x8/thread.
// ---------------------------------------------------------------------------
template <bool GATHER_A, bool SCATTER_OUT>
__global__ __launch_bounds__(256) void sgemm_kernel(
    const float* __restrict__ A, const float* __restrict__ W,
    const float* __restrict__ bias, float* __restrict__ out)
{
    __shared__ float As[8][128];   // transposed: As[k][m]
    __shared__ float Bs[8][128];

    const int tid = threadIdx.x;
    const int tx  = tid & 15;      // 0..15 (n dimension)
    const int ty  = tid >> 4;      // 0..15 (m dimension)

    const int m_base = blockIdx.y * 128;
    const int n_base = blockIdx.x * 128;

    // global load indices
    const int a_row  = tid >> 1;         // 0..127
    const int a_col4 = (tid & 1) * 4;    // 0 or 4
    const int b_row  = tid >> 5;         // 0..7
    const int b_col4 = (tid & 31) * 4;   // 0..124

    float acc[8][8];
#pragma unroll
    for (int i = 0; i < 8; i++)
#pragma unroll
        for (int j = 0; j < 8; j++) acc[i][j] = 0.0f;

    for (int k0 = 0; k0 < KDIM; k0 += 8) {
        // stage loads in registers
        float4 a4;
        if (GATHER_A) {
            const int m = m_base + a_row;
            const int b = m >> 11;           // m / 2048
            const int t = m & 2047;
            const int k = k0 + a_col4;
            const int h = k >> 7;            // k / 128
            const int d = k & 127;
            a4 = *(const float4*)&A[(((size_t)b * NH + h) * T + t) * DH + d];
        } else {
            a4 = *(const float4*)&A[(size_t)(m_base + a_row) * KDIM + k0 + a_col4];
        }
        const float4 b4 = *(const float4*)&W[(size_t)(k0 + b_row) * NDIM + n_base + b_col4];

        __syncthreads();   // prior compute done before overwriting smem
        As[a_col4 + 0][a_row] = a4.x;
        As[a_col4 + 1][a_row] = a4.y;
        As[a_col4 + 2][a_row] = a4.z;
        As[a_col4 + 3][a_row] = a4.w;
        *(float4*)&Bs[b_row][b_col4] = b4;
        __syncthreads();

#pragma unroll
        for (int kk = 0; kk < 8; kk++) {
            float af[8], bf[8];
            *(float4*)&af[0] = *(const float4*)&As[kk][ty * 8];
            *(float4*)&af[4] = *(const float4*)&As[kk][ty * 8 + 4];
            *(float4*)&bf[0] = *(const float4*)&Bs[kk][tx * 8];
            *(float4*)&bf[4] = *(const float4*)&Bs[kk][tx * 8 + 4];
#pragma unroll
            for (int i = 0; i < 8; i++)
#pragma unroll
                for (int j = 0; j < 8; j++)
                    acc[i][j] += af[i] * bf[j];
        }
    }

    // epilogue
#pragma unroll
    for (int i = 0; i < 8; i++) {
        const int m = m_base + ty * 8 + i;
#pragma unroll
        for (int j = 0; j < 8; j += 4) {
            const int n = n_base + tx * 8 + j;
            float4 r;
            r.x = acc[i][j + 0] + bias[n + 0];
            r.y = acc[i][j + 1] + bias[n + 1];
            r.z = acc[i][j + 2] + bias[n + 2];
            r.w = acc[i][j + 3] + bias[n + 3];
            if (SCATTER_OUT) {
                const int b = m >> 11, t = m & 2047;
                const int h = n >> 7, d = n & 127;
                *(float4*)&out[(((size_t)b * NH + h) * T + t) * DH + d] = r;
            } else {
                *(float4*)&out[(size_t)m * NDIM + n] = r;
            }
        }
    }
}

// ---------------------------------------------------------------------------
// Flash attention (causal), per-head. BQ=BKV=64, D=128, 256 threads.
// Dynamic smem layout (floats):
//   Qs[64][132] Ks[64][132] Vs[64][132] Ps[64][68] red[64][17]
//   row_m[64] row_l[64] row_scale[64]
// ---------------------------------------------------------------------------
#define BQ  64
#define BKV 64
#define PADW (DH + 4)       // 132
#define PPAD (BKV + 4)      // 68

#define QS_OFF   0
#define KS_OFF   (QS_OFF + BQ * PADW)
#define VS_OFF   (KS_OFF + BKV * PADW)
#define PS_OFF   (VS_OFF + BKV * PADW)
#define RED_OFF  (PS_OFF + BQ * PPAD)
#define RM_OFF   (RED_OFF + BQ * 17)
#define RL_OFF   (RM_OFF + BQ)
#define RS_OFF   (RL_OFF + BQ)
#define FLASH_SMEM_FLOATS (RS_OFF + BQ)
#define FLASH_SMEM_BYTES  (FLASH_SMEM_FLOATS * 4)   // 123904

__global__ __launch_bounds__(256) void flash_kernel(
    const float* __restrict__ gq, const float* __restrict__ gk,
    const float* __restrict__ gv, float* __restrict__ gout)
{
    extern __shared__ float sm[];
    float (*Qs)[PADW] = (float (*)[PADW])(sm + QS_OFF);
    float (*Ks)[PADW] = (float (*)[PADW])(sm + KS_OFF);
    float (*Vs)[PADW] = (float (*)[PADW])(sm + VS_OFF);
    float (*Ps)[PPAD] = (float (*)[PPAD])(sm + PS_OFF);
    float (*red)[17]  = (float (*)[17])(sm + RED_OFF);
    float* row_m = sm + RM_OFF;
    float* row_l = sm + RL_OFF;
    float* row_s = sm + RS_OFF;

    const int tid = threadIdx.x;
    const int tx  = tid & 15;   // column group
    const int ty  = tid >> 4;   // row group
    const int r0  = ty * 4;     // 4 S-rows per thread
    const int c0  = tx * 4;     // 4 S-cols per thread
    const int cn0 = tx * 8;     // 8 O-cols per thread

    const int qt = blockIdx.x;            // query tile
    const int h  = blockIdx.y;
    const int b  = blockIdx.z;
    const int q0 = qt * BQ;

    const size_t head_off = ((size_t)b * NH + h) * T * DH;
    const float* qbase = gq + head_off;
    const float* kbase = gk + head_off;
    const float* vbase = gv + head_off;

    const float NEG_INF = __int_as_float(0xff800000);
    const float scale   = 0.08838834764831845f;   // 1/sqrt(128)

    // init row state + load Q tile
    if (tid < BQ) { row_m[tid] = NEG_INF; row_l[tid] = 0.0f; }
    for (int i = tid; i < BQ * (DH / 4); i += 256) {
        const int r  = i >> 5;          // DH/4 = 32
        const int c4 = (i & 31) * 4;
        *(float4*)&Qs[r][c4] = *(const float4*)&qbase[(size_t)(q0 + r) * DH + c4];
    }

    float o[4][8];
#pragma unroll
    for (int i = 0; i < 4; i++)
#pragma unroll
        for (int j = 0; j < 8; j++) o[i][j] = 0.0f;

    for (int kt = 0; kt <= qt; kt++) {
        const int kv0 = kt * BKV;
        const bool diag = (kt == qt);

        __syncthreads();   // prior tile done with Ks/Vs/Ps/red
        for (int i = tid; i < BKV * (DH / 4); i += 256) {
            const int r  = i >> 5;
            const int c4 = (i & 31) * 4;
            *(float4*)&Ks[r][c4] = *(const float4*)&kbase[(size_t)(kv0 + r) * DH + c4];
            *(float4*)&Vs[r][c4] = *(const float4*)&vbase[(size_t)(kv0 + r) * DH + c4];
        }
        __syncthreads();

        // S = Q K^T (4x4 per thread)
        float s[4][4];
#pragma unroll
        for (int i = 0; i < 4; i++)
#pragma unroll
            for (int j = 0; j < 4; j++) s[i][j] = 0.0f;

        for (int d = 0; d < DH; d += 4) {
            float4 qv[4], kv[4];
#pragma unroll
            for (int i = 0; i < 4; i++) qv[i] = *(const float4*)&Qs[r0 + i][d];
#pragma unroll
            for (int j = 0; j < 4; j++) kv[j] = *(const float4*)&Ks[c0 + j][d];
#pragma unroll
            for (int i = 0; i < 4; i++)
#pragma unroll
                for (int j = 0; j < 4; j++)
                    s[i][j] += qv[i].x * kv[j].x + qv[i].y * kv[j].y +
                               qv[i].z * kv[j].z + qv[i].w * kv[j].w;
        }

        // scale + causal mask, per-thread row maxima
        float lm[4];
#pragma unroll
        for (int i = 0; i < 4; i++) {
            lm[i] = NEG_INF;
#pragma unroll
            for (int j = 0; j < 4; j++) {
                float val = s[i][j] * scale;
                if (diag && (kv0 + c0 + j > q0 + r0 + i)) val = NEG_INF;
                s[i][j] = val;
                lm[i] = fmaxf(lm[i], val);
            }
            red[r0 + i][tx] = lm[i];
        }
        __syncthreads();

        if (tid < BQ) {
            float mt = red[tid][0];
#pragma unroll
            for (int t2 = 1; t2 < 16; t2++) mt = fmaxf(mt, red[tid][t2]);
            const float mo = row_m[tid];
            const float mn = fmaxf(mo, mt);
            row_m[tid] = mn;
            const float sc = __expf(mo - mn);   // exp(-inf)=0 on first tile
            row_s[tid] = sc;
            row_l[tid] *= sc;
        }
        __syncthreads();

        // P = exp(S - m_new), partial row sums, rescale O
#pragma unroll
        for (int i = 0; i < 4; i++) {
            const float mn = row_m[r0 + i];
            float ls = 0.0f;
#pragma unroll
            for (int j = 0; j < 4; j++) {
                const float p = __expf(s[i][j] - mn);
                Ps[r0 + i][c0 + j] = p;
                ls += p;
            }
            red[r0 + i][tx] = ls;
            const float sc = row_s[r0 + i];
#pragma unroll
            for (int j = 0; j < 8; j++) o[i][j] *= sc;
        }
        __syncthreads();

        if (tid < BQ) {
            float su = red[tid][0];
#pragma unroll
            for (int t2 = 1; t2 < 16; t2++) su += red[tid][t2];
            row_l[tid] += su;
        }

        // O += P V
        for (int kk = 0; kk < BKV; kk++) {
            const float4 v0 = *(const float4*)&Vs[kk][cn0];
            const float4 v1 = *(const float4*)&Vs[kk][cn0 + 4];
#pragma unroll
            for (int i = 0; i < 4; i++) {
                const float p = Ps[r0 + i][kk];
                o[i][0] += p * v0.x; o[i][1] += p * v0.y;
                o[i][2] += p * v0.z; o[i][3] += p * v0.w;
                o[i][4] += p * v1.x; o[i][5] += p * v1.y;
                o[i][6] += p * v1.z; o[i][7] += p * v1.w;
            }
        }
    }

    __syncthreads();   // row_l final
#pragma unroll
    for (int i = 0; i < 4; i++) {
        const float inv = 1.0f / row_l[r0 + i];
        float4 w0, w1;
        w0.x = o[i][0] * inv; w0.y = o[i][1] * inv;
        w0.z = o[i][2] * inv; w0.w = o[i][3] * inv;
        w1.x = o[i][4] * inv; w1.y = o[i][5] * inv;
        w1.z = o[i][6] * inv; w1.w = o[i][7] * inv;
        float* dst = gout + head_off + (size_t)(q0 + r0 + i) * DH + cn0;
        *(float4*)&dst[0] = w0;
        *(float4*)&dst[4] = w1;
    }
}

// ---------------------------------------------------------------------------
extern "C" void kernel_launch(void* const* d_in, const int* in_sizes, int n_in,
                              void* d_out, int out_size)
{
    const float* src = (const float*)d_in[0];
    const float* Wq  = (const float*)d_in[1];
    const float* bq  = (const float*)d_in[2];
    const float* Wk  = (const float*)d_in[3];
    const float* bk  = (const float*)d_in[4];
    const float* Wv  = (const float*)d_in[5];
    const float* bv  = (const float*)d_in[6];
    const float* Wo  = (const float*)d_in[7];
    const float* bo  = (const float*)d_in[8];
    float* out = (float*)d_out;

    float *q, *k, *v, *o;
    cudaGetSymbolAddress((void**)&q, g_q);
    cudaGetSymbolAddress((void**)&k, g_k);
    cudaGetSymbolAddress((void**)&v, g_v);
    cudaGetSymbolAddress((void**)&o, g_o);

    cudaFuncSetAttribute(flash_kernel,
                         cudaFuncAttributeMaxDynamicSharedMemorySize,
                         FLASH_SMEM_BYTES);

    const dim3 gemm_grid(NDIM / 128, MROWS / 128);   // (16, 32)
    const dim3 gemm_blk(256);

    sgemm_kernel<false, true><<<gemm_grid, gemm_blk>>>(src, Wq, bq, q);
    sgemm_kernel<false, true><<<gemm_grid, gemm_blk>>>(src, Wk, bk, k);
    sgemm_kernel<false, true><<<gemm_grid, gemm_blk>>>(src, Wv, bv, v);

    flash_kernel<<<dim3(T / BQ, NH, BSZ), 256, FLASH_SMEM_BYTES>>>(q, k, v, o);

    sgemm_kernel<true, false><<<gemm_grid, gemm_blk>>>(o, Wo, bo, out);
}

// round 5
// speedup vs baseline: 1.8657x; 1.8625x over previous
#include <cuda_runtime.h>
#include <math.h>
#include <stdint.h>

// Problem constants
#define BSZ 2
#define T   2048
#define C   2048
#define NH  16
#define DH  128
#define MROWS (BSZ * T)      // 4096
#define KDIM  C              // 2048
#define NDIM  C              // 2048

// Scratch
__device__ float g_q[BSZ * NH * T * DH];
__device__ float g_k[BSZ * NH * T * DH];
__device__ float g_v[BSZ * NH * T * DH];
__device__ float g_o[BSZ * NH * T * DH];
__device__ float g_a[MROWS * KDIM];      // tf32-rounded src
__device__ float g_wt[KDIM * NDIM];      // rounded weight, native [K][N] layout

// ---------------------------------------------------------------------------
// PTX helpers (compute_103-safe: mma.sync + cp.async only)
// ---------------------------------------------------------------------------
__device__ __forceinline__ uint32_t smem_u32(const void* p) {
    uint32_t a;
    asm("{ .reg .u64 t; cvta.to.shared.u64 t, %1; cvt.u32.u64 %0, t; }"
        : "=r"(a) : "l"(p));
    return a;
}

__device__ __forceinline__ float rna_tf32(float x) {
    uint32_t r;
    asm("cvt.rna.tf32.f32 %0, %1;" : "=r"(r) : "f"(x));
    return __uint_as_float(r);
}

__device__ __forceinline__ void cp16(uint32_t dst, const float* src) {
    asm volatile("cp.async.cg.shared.global [%0], [%1], 16;"
                 :: "r"(dst), "l"(src));
}
#define CP_COMMIT() asm volatile("cp.async.commit_group;" ::: "memory")
template <int N>
__device__ __forceinline__ void cp_wait() {
    asm volatile("cp.async.wait_group %0;" :: "n"(N) : "memory");
}

__device__ __forceinline__ void mma_tf32_16n8k8(
    float& d0, float& d1, float& d2, float& d3,
    uint32_t a0, uint32_t a1, uint32_t a2, uint32_t a3,
    uint32_t b0, uint32_t b1)
{
    asm volatile(
        "mma.sync.aligned.m16n8k8.row.col.f32.tf32.tf32.f32 "
        "{%0,%1,%2,%3}, {%4,%5,%6,%7}, {%8,%9}, {%0,%1,%2,%3};\n"
        : "+f"(d0), "+f"(d1), "+f"(d2), "+f"(d3)
        : "r"(a0), "r"(a1), "r"(a2), "r"(a3), "r"(b0), "r"(b1));
}

// ---------------------------------------------------------------------------
// Pre-pass: tf32 RNA rounding
// ---------------------------------------------------------------------------
__global__ void round_tf32_kernel(const float4* __restrict__ in,
                                  float4* __restrict__ out, int n4) {
    int i = blockIdx.x * blockDim.x + threadIdx.x;
    int stride = gridDim.x * blockDim.x;
    for (; i < n4; i += stride) {
        float4 v = in[i];
        v.x = rna_tf32(v.x); v.y = rna_tf32(v.y);
        v.z = rna_tf32(v.z); v.w = rna_tf32(v.w);
        out[i] = v;
    }
}

// ---------------------------------------------------------------------------
// HMMA tf32 GEMM: out[M=4096, N=2048] = A[M,K=2048] @ W[K,N] + bias
// 128x128 block tile, K-slab 32, 3-stage cp.async pipeline, 256 threads,
// 8 warps (2x4), warp tile 64x32, mma.sync m16n8k8 tf32.
//   A smem: [128][36] floats per stage (bank-conflict-free a-frag reads)
//   B smem: [32][136] floats per stage (bank-conflict-free b-frag reads)
//   GATHER_A:    A read from heads layout [B,N,T,D]
//   SCATTER_OUT: out written to heads layout [B,N,T,D]
// ---------------------------------------------------------------------------
#define BK 32
#define NKS (KDIM / BK)          // 64
#define STAGES 3
#define AS_STRIDE 36
#define BS_STRIDE 136
#define A_ST_FLOATS (128 * AS_STRIDE)            // 4608
#define B_ST_FLOATS (BK * BS_STRIDE)             // 4352
#define ST_FLOATS (A_ST_FLOATS + B_ST_FLOATS)    // 8960
#define GEMM_SMEM (STAGES * ST_FLOATS * 4)       // 107520 bytes

template <bool GATHER_A, bool SCATTER_OUT>
__global__ __launch_bounds__(256, 2) void tc_gemm(
    const float* __restrict__ A, const float* __restrict__ W,
    const float* __restrict__ bias, float* __restrict__ out)
{
    extern __shared__ float smf[];
    const uint32_t sb = smem_u32(smf);
    const int tid  = threadIdx.x;
    const int lane = tid & 31;
    const int w    = tid >> 5;
    const int wm   = (w >> 2) * 64;    // warp m offset (0 or 64)
    const int wn   = (w & 3) * 32;     // warp n offset (0..96)

    const int m_base = blockIdx.y * 128;
    const int n_base = blockIdx.x * 128;

    // ---- load geometry: 4 granules (16B) per operand per slab per thread ----
    uint32_t a_off[4], b_off[4];
    const float* a_fix[4];
    const float* b_fix[4];
#pragma unroll
    for (int i = 0; i < 4; i++) {
        const int g  = tid + i * 256;
        const int ar = g >> 3;          // 0..127  (m row)
        const int ac = g & 7;           // 16B chunk in 128B k-row
        a_off[i] = (uint32_t)(ar * AS_STRIDE + ac * 4) * 4;
        if (GATHER_A) {
            const int m = m_base + ar;
            a_fix[i] = A + (size_t)(m >> 11) * (NH * T * DH)
                         + (size_t)(m & 2047) * DH + ac * 4;
        } else {
            a_fix[i] = A + (size_t)(m_base + ar) * KDIM + ac * 4;
        }
        const int br = g >> 5;          // 0..31  (k row)
        const int bc = g & 31;          // 16B chunk in 512B n-row
        b_off[i] = (uint32_t)(A_ST_FLOATS + br * BS_STRIDE + bc * 4) * 4;
        b_fix[i] = W + (size_t)br * NDIM + n_base + bc * 4;
    }

    auto load_slab = [&](int ks) {
        const int s = ks % STAGES;
        const uint32_t stage = sb + (uint32_t)(s * ST_FLOATS) * 4;
        const int k0 = ks * BK;
#pragma unroll
        for (int i = 0; i < 4; i++) {
            const float* asrc;
            if (GATHER_A)
                asrc = a_fix[i] + (size_t)(k0 >> 7) * (T * DH) + (k0 & 127);
            else
                asrc = a_fix[i] + k0;
            cp16(stage + a_off[i], asrc);
            cp16(stage + b_off[i], b_fix[i] + (size_t)k0 * NDIM);
        }
        CP_COMMIT();
    };

    float acc[4][4][4];   // [mf][nf][reg]
#pragma unroll
    for (int mf = 0; mf < 4; mf++)
#pragma unroll
        for (int nf = 0; nf < 4; nf++)
#pragma unroll
            for (int r = 0; r < 4; r++) acc[mf][nf][r] = 0.0f;

    load_slab(0);
    load_slab(1);

    const int qr = lane >> 2;   // 0..7
    const int qc = lane & 3;    // 0..3

    for (int ks = 0; ks < NKS; ks++) {
        if (ks >= NKS - 1) cp_wait<0>(); else cp_wait<1>();
        __syncthreads();

        // prefetch next slab (stage being overwritten finished last iter)
        if (ks + 2 < NKS) load_slab(ks + 2);

        const float* st = smf + (ks % STAGES) * ST_FLOATS;
        const float* As = st;                       // [128][36]
        const float* Bs = st + A_ST_FLOATS;         // [32][136]

#pragma unroll
        for (int kk = 0; kk < 4; kk++) {
            const int kb = kk * 8;
            // B fragments: 4 n-frags x 2 regs
            uint32_t bfr[4][2];
#pragma unroll
            for (int nf = 0; nf < 4; nf++) {
                const int cn = wn + nf * 8 + qr;
                bfr[nf][0] = __float_as_uint(Bs[(kb + qc)     * BS_STRIDE + cn]);
                bfr[nf][1] = __float_as_uint(Bs[(kb + qc + 4) * BS_STRIDE + cn]);
            }
#pragma unroll
            for (int mf = 0; mf < 4; mf++) {
                const int r0 = wm + mf * 16 + qr;
                const uint32_t a0 = __float_as_uint(As[r0      * AS_STRIDE + kb + qc]);
                const uint32_t a1 = __float_as_uint(As[(r0 + 8)* AS_STRIDE + kb + qc]);
                const uint32_t a2 = __float_as_uint(As[r0      * AS_STRIDE + kb + qc + 4]);
                const uint32_t a3 = __float_as_uint(As[(r0 + 8)* AS_STRIDE + kb + qc + 4]);
#pragma unroll
                for (int nf = 0; nf < 4; nf++)
                    mma_tf32_16n8k8(acc[mf][nf][0], acc[mf][nf][1],
                                    acc[mf][nf][2], acc[mf][nf][3],
                                    a0, a1, a2, a3, bfr[nf][0], bfr[nf][1]);
            }
        }
        __syncthreads();
    }

    // ---- epilogue: bias + store (optionally scatter to heads layout) ----
#pragma unroll
    for (int mf = 0; mf < 4; mf++) {
        const int row0 = m_base + wm + mf * 16 + qr;
#pragma unroll
        for (int nf = 0; nf < 4; nf++) {
            const int col = n_base + wn + nf * 8 + 2 * qc;
            const float bx = bias[col];
            const float by = bias[col + 1];
#pragma unroll
            for (int half = 0; half < 2; half++) {
                const int row = row0 + half * 8;
                float2 v;
                v.x = acc[mf][nf][half * 2 + 0] + bx;
                v.y = acc[mf][nf][half * 2 + 1] + by;
                if (SCATTER_OUT) {
                    const int b = row >> 11, t = row & 2047;
                    const int h = col >> 7,  d = col & 127;
                    *(float2*)&out[(((size_t)b * NH + h) * T + t) * DH + d] = v;
                } else {
                    *(float2*)&out[(size_t)row * NDIM + col] = v;
                }
            }
        }
    }
}

// ---------------------------------------------------------------------------
// Flash attention (causal), per-head. BQ=BKV=64, D=128, 256 threads. (fp32)
// ---------------------------------------------------------------------------
#define BQ  64
#define BKV 64
#define PADW (DH + 4)       // 132
#define PPAD (BKV + 4)      // 68

#define QS_OFF   0
#define KS_OFF   (QS_OFF + BQ * PADW)
#define VS_OFF   (KS_OFF + BKV * PADW)
#define PS_OFF   (VS_OFF + BKV * PADW)
#define RED_OFF  (PS_OFF + BQ * PPAD)
#define RM_OFF   (RED_OFF + BQ * 17)
#define RL_OFF   (RM_OFF + BQ)
#define RS_OFF   (RL_OFF + BQ)
#define FLASH_SMEM_FLOATS (RS_OFF + BQ)
#define FLASH_SMEM_BYTES  (FLASH_SMEM_FLOATS * 4)

__global__ __launch_bounds__(256) void flash_kernel(
    const float* __restrict__ gq, const float* __restrict__ gk,
    const float* __restrict__ gv, float* __restrict__ gout)
{
    extern __shared__ float sm[];
    float (*Qs)[PADW] = (float (*)[PADW])(sm + QS_OFF);
    float (*Ks)[PADW] = (float (*)[PADW])(sm + KS_OFF);
    float (*Vs)[PADW] = (float (*)[PADW])(sm + VS_OFF);
    float (*Ps)[PPAD] = (float (*)[PPAD])(sm + PS_OFF);
    float (*red)[17]  = (float (*)[17])(sm + RED_OFF);
    float* row_m = sm + RM_OFF;
    float* row_l = sm + RL_OFF;
    float* row_s = sm + RS_OFF;

    const int tid = threadIdx.x;
    const int tx  = tid & 15;
    const int ty  = tid >> 4;
    const int r0  = ty * 4;
    const int c0  = tx * 4;
    const int cn0 = tx * 8;

    const int qt = blockIdx.x;
    const int h  = blockIdx.y;
    const int b  = blockIdx.z;
    const int q0 = qt * BQ;

    const size_t head_off = ((size_t)b * NH + h) * T * DH;
    const float* qbase = gq + head_off;
    const float* kbase = gk + head_off;
    const float* vbase = gv + head_off;

    const float NEG_INF = __int_as_float(0xff800000);
    const float scale   = 0.08838834764831845f;

    if (tid < BQ) { row_m[tid] = NEG_INF; row_l[tid] = 0.0f; }
    for (int i = tid; i < BQ * (DH / 4); i += 256) {
        const int r  = i >> 5;
        const int c4 = (i & 31) * 4;
        *(float4*)&Qs[r][c4] = *(const float4*)&qbase[(size_t)(q0 + r) * DH + c4];
    }

    float o[4][8];
#pragma unroll
    for (int i = 0; i < 4; i++)
#pragma unroll
        for (int j = 0; j < 8; j++) o[i][j] = 0.0f;

    for (int kt = 0; kt <= qt; kt++) {
        const int kv0 = kt * BKV;
        const bool diag = (kt == qt);

        __syncthreads();
        for (int i = tid; i < BKV * (DH / 4); i += 256) {
            const int r  = i >> 5;
            const int c4 = (i & 31) * 4;
            *(float4*)&Ks[r][c4] = *(const float4*)&kbase[(size_t)(kv0 + r) * DH + c4];
            *(float4*)&Vs[r][c4] = *(const float4*)&vbase[(size_t)(kv0 + r) * DH + c4];
        }
        __syncthreads();

        float s[4][4];
#pragma unroll
        for (int i = 0; i < 4; i++)
#pragma unroll
            for (int j = 0; j < 4; j++) s[i][j] = 0.0f;

        for (int d = 0; d < DH; d += 4) {
            float4 qv[4], kv[4];
#pragma unroll
            for (int i = 0; i < 4; i++) qv[i] = *(const float4*)&Qs[r0 + i][d];
#pragma unroll
            for (int j = 0; j < 4; j++) kv[j] = *(const float4*)&Ks[c0 + j][d];
#pragma unroll
            for (int i = 0; i < 4; i++)
#pragma unroll
                for (int j = 0; j < 4; j++)
                    s[i][j] += qv[i].x * kv[j].x + qv[i].y * kv[j].y +
                               qv[i].z * kv[j].z + qv[i].w * kv[j].w;
        }

        float lm[4];
#pragma unroll
        for (int i = 0; i < 4; i++) {
            lm[i] = NEG_INF;
#pragma unroll
            for (int j = 0; j < 4; j++) {
                float val = s[i][j] * scale;
                if (diag && (kv0 + c0 + j > q0 + r0 + i)) val = NEG_INF;
                s[i][j] = val;
                lm[i] = fmaxf(lm[i], val);
            }
            red[r0 + i][tx] = lm[i];
        }
        __syncthreads();

        if (tid < BQ) {
            float mt = red[tid][0];
#pragma unroll
            for (int t2 = 1; t2 < 16; t2++) mt = fmaxf(mt, red[tid][t2]);
            const float mo = row_m[tid];
            const float mn = fmaxf(mo, mt);
            row_m[tid] = mn;
            const float sc = __expf(mo - mn);
            row_s[tid] = sc;
            row_l[tid] *= sc;
        }
        __syncthreads();

#pragma unroll
        for (int i = 0; i < 4; i++) {
            const float mn = row_m[r0 + i];
            float ls = 0.0f;
#pragma unroll
            for (int j = 0; j < 4; j++) {
                const float p = __expf(s[i][j] - mn);
                Ps[r0 + i][c0 + j] = p;
                ls += p;
            }
            red[r0 + i][tx] = ls;
            const float sc = row_s[r0 + i];
#pragma unroll
            for (int j = 0; j < 8; j++) o[i][j] *= sc;
        }
        __syncthreads();

        if (tid < BQ) {
            float su = red[tid][0];
#pragma unroll
            for (int t2 = 1; t2 < 16; t2++) su += red[tid][t2];
            row_l[tid] += su;
        }

        for (int kk = 0; kk < BKV; kk++) {
            const float4 v0 = *(const float4*)&Vs[kk][cn0];
            const float4 v1 = *(const float4*)&Vs[kk][cn0 + 4];
#pragma unroll
            for (int i = 0; i < 4; i++) {
                const float p = Ps[r0 + i][kk];
                o[i][0] += p * v0.x; o[i][1] += p * v0.y;
                o[i][2] += p * v0.z; o[i][3] += p * v0.w;
                o[i][4] += p * v1.x; o[i][5] += p * v1.y;
                o[i][6] += p * v1.z; o[i][7] += p * v1.w;
            }
        }
    }

    __syncthreads();
#pragma unroll
    for (int i = 0; i < 4; i++) {
        const float inv = 1.0f / row_l[r0 + i];
        float4 w0, w1;
        w0.x = o[i][0] * inv; w0.y = o[i][1] * inv;
        w0.z = o[i][2] * inv; w0.w = o[i][3] * inv;
        w1.x = o[i][4] * inv; w1.y = o[i][5] * inv;
        w1.z = o[i][6] * inv; w1.w = o[i][7] * inv;
        float* dst = gout + head_off + (size_t)(q0 + r0 + i) * DH + cn0;
        *(float4*)&dst[0] = w0;
        *(float4*)&dst[4] = w1;
    }
}

// ---------------------------------------------------------------------------
extern "C" void kernel_launch(void* const* d_in, const int* in_sizes, int n_in,
                              void* d_out, int out_size)
{
    const float* src = (const float*)d_in[0];
    const float* Wq  = (const float*)d_in[1];
    const float* bq  = (const float*)d_in[2];
    const float* Wk  = (const float*)d_in[3];
    const float* bk  = (const float*)d_in[4];
    const float* Wv  = (const float*)d_in[5];
    const float* bv  = (const float*)d_in[6];
    const float* Wo  = (const float*)d_in[7];
    const float* bo  = (const float*)d_in[8];
    float* out = (float*)d_out;

    float *q, *k, *v, *o, *a, *wt;
    cudaGetSymbolAddress((void**)&q,  g_q);
    cudaGetSymbolAddress((void**)&k,  g_k);
    cudaGetSymbolAddress((void**)&v,  g_v);
    cudaGetSymbolAddress((void**)&o,  g_o);
    cudaGetSymbolAddress((void**)&a,  g_a);
    cudaGetSymbolAddress((void**)&wt, g_wt);

    cudaFuncSetAttribute(flash_kernel,
                         cudaFuncAttributeMaxDynamicSharedMemorySize,
                         FLASH_SMEM_BYTES);
    cudaFuncSetAttribute(tc_gemm<false, true>,
                         cudaFuncAttributeMaxDynamicSharedMemorySize, GEMM_SMEM);
    cudaFuncSetAttribute(tc_gemm<true, false>,
                         cudaFuncAttributeMaxDynamicSharedMemorySize, GEMM_SMEM);

    const dim3 ggrid(NDIM / 128, MROWS / 128);   // (16, 32)
    const int NW4 = KDIM * NDIM / 4;

    // Round activations once.
    round_tf32_kernel<<<1024, 256>>>((const float4*)src, (float4*)a,
                                     MROWS * KDIM / 4);

    // Q/K/V projections on HMMA tf32.
    round_tf32_kernel<<<1024, 256>>>((const float4*)Wq, (float4*)wt, NW4);
    tc_gemm<false, true><<<ggrid, 256, GEMM_SMEM>>>(a, wt, bq, q);
    round_tf32_kernel<<<1024, 256>>>((const float4*)Wk, (float4*)wt, NW4);
    tc_gemm<false, true><<<ggrid, 256, GEMM_SMEM>>>(a, wt, bk, k);
    round_tf32_kernel<<<1024, 256>>>((const float4*)Wv, (float4*)wt, NW4);
    tc_gemm<false, true><<<ggrid, 256, GEMM_SMEM>>>(a, wt, bv, v);

    // Attention (fp32 flash).
    flash_kernel<<<dim3(T / BQ, NH, BSZ), 256, FLASH_SMEM_BYTES>>>(q, k, v, o);

    // O projection: round attention output, then HMMA tf32 with gather.
    round_tf32_kernel<<<1024, 256>>>((const float4*)o, (float4*)o,
                                     BSZ * NH * T * DH / 4);
    round_tf32_kernel<<<1024, 256>>>((const float4*)Wo, (float4*)wt, NW4);
    tc_gemm<true, false><<<ggrid, 256, GEMM_SMEM>>>(o, wt, bo, out);
}

// round 6
// speedup vs baseline: 4.3670x; 2.3408x over previous
#include <cuda_runtime.h>
#include <math.h>
#include <stdint.h>

// Problem constants
#define BSZ 2
#define T   2048
#define C   2048
#define NH  16
#define DH  128
#define MROWS (BSZ * T)      // 4096
#define KDIM  C              // 2048
#define NDIM  C              // 2048

// Scratch
__device__ float g_q[BSZ * NH * T * DH];
__device__ float g_k[BSZ * NH * T * DH];
__device__ float g_v[BSZ * NH * T * DH];
__device__ float g_o[BSZ * NH * T * DH];
__device__ float g_a[MROWS * KDIM];      // tf32-rounded src
__device__ float g_wt[KDIM * NDIM];      // rounded weight, native [K][N] layout

// ---------------------------------------------------------------------------
// PTX helpers (compute_103-safe: mma.sync + cp.async only)
// ---------------------------------------------------------------------------
__device__ __forceinline__ uint32_t smem_u32(const void* p) {
    uint32_t a;
    asm("{ .reg .u64 t; cvta.to.shared.u64 t, %1; cvt.u32.u64 %0, t; }"
        : "=r"(a) : "l"(p));
    return a;
}

__device__ __forceinline__ float rna_tf32(float x) {
    uint32_t r;
    asm("cvt.rna.tf32.f32 %0, %1;" : "=r"(r) : "f"(x));
    return __uint_as_float(r);
}

__device__ __forceinline__ void cp16(uint32_t dst, const float* src) {
    asm volatile("cp.async.cg.shared.global [%0], [%1], 16;"
                 :: "r"(dst), "l"(src));
}
#define CP_COMMIT() asm volatile("cp.async.commit_group;" ::: "memory")
template <int N>
__device__ __forceinline__ void cp_wait() {
    asm volatile("cp.async.wait_group %0;" :: "n"(N) : "memory");
}

__device__ __forceinline__ void mma_tf32_16n8k8(
    float& d0, float& d1, float& d2, float& d3,
    uint32_t a0, uint32_t a1, uint32_t a2, uint32_t a3,
    uint32_t b0, uint32_t b1)
{
    asm volatile(
        "mma.sync.aligned.m16n8k8.row.col.f32.tf32.tf32.f32 "
        "{%0,%1,%2,%3}, {%4,%5,%6,%7}, {%8,%9}, {%0,%1,%2,%3};\n"
        : "+f"(d0), "+f"(d1), "+f"(d2), "+f"(d3)
        : "r"(a0), "r"(a1), "r"(a2), "r"(a3), "r"(b0), "r"(b1));
}

// ---------------------------------------------------------------------------
// Pre-pass: tf32 RNA rounding
// ---------------------------------------------------------------------------
__global__ void round_tf32_kernel(const float4* __restrict__ in,
                                  float4* __restrict__ out, int n4) {
    int i = blockIdx.x * blockDim.x + threadIdx.x;
    int stride = gridDim.x * blockDim.x;
    for (; i < n4; i += stride) {
        float4 v = in[i];
        v.x = rna_tf32(v.x); v.y = rna_tf32(v.y);
        v.z = rna_tf32(v.z); v.w = rna_tf32(v.w);
        out[i] = v;
    }
}

// ---------------------------------------------------------------------------
// HMMA tf32 GEMM: out[M=4096, N=2048] = A[M,K=2048] @ W[K,N] + bias
// 128x128 block tile, K-slab 32, 3-stage cp.async pipeline, 256 threads,
// 8 warps (2x4), warp tile 64x32, mma.sync m16n8k8 tf32.
//   GATHER_A:    A read from heads layout [B,N,T,D]
//   SCATTER_OUT: out written to heads layout [B,N,T,D]
//   ROUND_OUT:   RNA-round the stored result to tf32 (feeds another tf32 mma)
// ---------------------------------------------------------------------------
#define BK 32
#define NKS (KDIM / BK)          // 64
#define STAGES 3
#define AS_STRIDE 36
#define BS_STRIDE 136
#define A_ST_FLOATS (128 * AS_STRIDE)            // 4608
#define B_ST_FLOATS (BK * BS_STRIDE)             // 4352
#define ST_FLOATS (A_ST_FLOATS + B_ST_FLOATS)    // 8960
#define GEMM_SMEM (STAGES * ST_FLOATS * 4)       // 107520 bytes

template <bool GATHER_A, bool SCATTER_OUT, bool ROUND_OUT>
__global__ __launch_bounds__(256, 2) void tc_gemm(
    const float* __restrict__ A, const float* __restrict__ W,
    const float* __restrict__ bias, float* __restrict__ out)
{
    extern __shared__ float smf[];
    const uint32_t sb = smem_u32(smf);
    const int tid  = threadIdx.x;
    const int lane = tid & 31;
    const int w    = tid >> 5;
    const int wm   = (w >> 2) * 64;    // warp m offset (0 or 64)
    const int wn   = (w & 3) * 32;     // warp n offset (0..96)

    const int m_base = blockIdx.y * 128;
    const int n_base = blockIdx.x * 128;

    // ---- load geometry: 4 granules (16B) per operand per slab per thread ----
    uint32_t a_off[4], b_off[4];
    const float* a_fix[4];
    const float* b_fix[4];
#pragma unroll
    for (int i = 0; i < 4; i++) {
        const int g  = tid + i * 256;
        const int ar = g >> 3;          // 0..127  (m row)
        const int ac = g & 7;           // 16B chunk in 128B k-row
        a_off[i] = (uint32_t)(ar * AS_STRIDE + ac * 4) * 4;
        if (GATHER_A) {
            const int m = m_base + ar;
            a_fix[i] = A + (size_t)(m >> 11) * (NH * T * DH)
                         + (size_t)(m & 2047) * DH + ac * 4;
        } else {
            a_fix[i] = A + (size_t)(m_base + ar) * KDIM + ac * 4;
        }
        const int br = g >> 5;          // 0..31  (k row)
        const int bc = g & 31;          // 16B chunk in 512B n-row
        b_off[i] = (uint32_t)(A_ST_FLOATS + br * BS_STRIDE + bc * 4) * 4;
        b_fix[i] = W + (size_t)br * NDIM + n_base + bc * 4;
    }

    auto load_slab = [&](int ks) {
        const int s = ks % STAGES;
        const uint32_t stage = sb + (uint32_t)(s * ST_FLOATS) * 4;
        const int k0 = ks * BK;
#pragma unroll
        for (int i = 0; i < 4; i++) {
            const float* asrc;
            if (GATHER_A)
                asrc = a_fix[i] + (size_t)(k0 >> 7) * (T * DH) + (k0 & 127);
            else
                asrc = a_fix[i] + k0;
            cp16(stage + a_off[i], asrc);
            cp16(stage + b_off[i], b_fix[i] + (size_t)k0 * NDIM);
        }
        CP_COMMIT();
    };

    float acc[4][4][4];   // [mf][nf][reg]
#pragma unroll
    for (int mf = 0; mf < 4; mf++)
#pragma unroll
        for (int nf = 0; nf < 4; nf++)
#pragma unroll
            for (int r = 0; r < 4; r++) acc[mf][nf][r] = 0.0f;

    load_slab(0);
    load_slab(1);

    const int qr = lane >> 2;   // 0..7
    const int qc = lane & 3;    // 0..3

    for (int ks = 0; ks < NKS; ks++) {
        if (ks >= NKS - 1) cp_wait<0>(); else cp_wait<1>();
        __syncthreads();

        // prefetch next slab (stage being overwritten finished last iter)
        if (ks + 2 < NKS) load_slab(ks + 2);

        const float* st = smf + (ks % STAGES) * ST_FLOATS;
        const float* As = st;                       // [128][36]
        const float* Bs = st + A_ST_FLOATS;         // [32][136]

#pragma unroll
        for (int kk = 0; kk < 4; kk++) {
            const int kb = kk * 8;
            // B fragments: 4 n-frags x 2 regs
            uint32_t bfr[4][2];
#pragma unroll
            for (int nf = 0; nf < 4; nf++) {
                const int cn = wn + nf * 8 + qr;
                bfr[nf][0] = __float_as_uint(Bs[(kb + qc)     * BS_STRIDE + cn]);
                bfr[nf][1] = __float_as_uint(Bs[(kb + qc + 4) * BS_STRIDE + cn]);
            }
#pragma unroll
            for (int mf = 0; mf < 4; mf++) {
                const int r0 = wm + mf * 16 + qr;
                const uint32_t a0 = __float_as_uint(As[r0      * AS_STRIDE + kb + qc]);
                const uint32_t a1 = __float_as_uint(As[(r0 + 8)* AS_STRIDE + kb + qc]);
                const uint32_t a2 = __float_as_uint(As[r0      * AS_STRIDE + kb + qc + 4]);
                const uint32_t a3 = __float_as_uint(As[(r0 + 8)* AS_STRIDE + kb + qc + 4]);
#pragma unroll
                for (int nf = 0; nf < 4; nf++)
                    mma_tf32_16n8k8(acc[mf][nf][0], acc[mf][nf][1],
                                    acc[mf][nf][2], acc[mf][nf][3],
                                    a0, a1, a2, a3, bfr[nf][0], bfr[nf][1]);
            }
        }
        __syncthreads();
    }

    // ---- epilogue: bias + store (optionally scatter / round) ----
#pragma unroll
    for (int mf = 0; mf < 4; mf++) {
        const int row0 = m_base + wm + mf * 16 + qr;
#pragma unroll
        for (int nf = 0; nf < 4; nf++) {
            const int col = n_base + wn + nf * 8 + 2 * qc;
            const float bx = bias[col];
            const float by = bias[col + 1];
#pragma unroll
            for (int half = 0; half < 2; half++) {
                const int row = row0 + half * 8;
                float2 v;
                v.x = acc[mf][nf][half * 2 + 0] + bx;
                v.y = acc[mf][nf][half * 2 + 1] + by;
                if (ROUND_OUT) { v.x = rna_tf32(v.x); v.y = rna_tf32(v.y); }
                if (SCATTER_OUT) {
                    const int b = row >> 11, t = row & 2047;
                    const int h = col >> 7,  d = col & 127;
                    *(float2*)&out[(((size_t)b * NH + h) * T + t) * DH + d] = v;
                } else {
                    *(float2*)&out[(size_t)row * NDIM + col] = v;
                }
            }
        }
    }
}

// ---------------------------------------------------------------------------
// Tensor-core flash attention (causal). BQ=128, BKV=64, D=128, 256 threads,
// 8 warps x 16 q-rows. tf32 mma for QK^T and PV; fp32 online softmax in
// registers with quad shfl reductions. Double-buffered cp.async K/V tiles.
// smem (floats): K[2][64][132], V[2][64][136], P[128][68]
// ---------------------------------------------------------------------------
#define FQ 128
#define FKV 64
#define KSTR 132
#define VSTR 136
#define PSTR 68
#define KST (FKV * KSTR)                 // 8448
#define VST (FKV * VSTR)                 // 8704
#define STG (KST + VST)                  // 17152
#define P_OFF (2 * STG)                  // 34304
#define FLASH2_SMEM ((P_OFF + FQ * PSTR) * 4)   // 172032 bytes

__global__ __launch_bounds__(256) void flash2_kernel(
    const float* __restrict__ gq, const float* __restrict__ gk,
    const float* __restrict__ gv, float* __restrict__ gout)
{
    extern __shared__ float sm[];
    const uint32_t sb = smem_u32(sm);
    const int tid  = threadIdx.x;
    const int lane = tid & 31;
    const int w    = tid >> 5;
    const int qr   = lane >> 2;
    const int qc   = lane & 3;

    const int qt = (int)gridDim.x - 1 - (int)blockIdx.x;  // heavy tiles first
    const int h  = blockIdx.y;
    const int b  = blockIdx.z;
    const int q0 = qt * FQ;
    const size_t head_off = ((size_t)b * NH + h) * T * DH;
    const float* qbase = gq + head_off;
    const float* kbase = gk + head_off;
    const float* vbase = gv + head_off;

    const int ntiles = 2 * qt + 2;
    const float scale = 0.08838834764831845f;   // 1/sqrt(128)

    // ---- Q fragments (held in registers for whole kernel) ----
    const int r0g = q0 + w * 16 + qr;
    float qf[16][4];
#pragma unroll
    for (int ks = 0; ks < 16; ks++) {
        const float* p0 = qbase + (size_t)r0g * DH + ks * 8 + qc;
        const float* p1 = qbase + (size_t)(r0g + 8) * DH + ks * 8 + qc;
        qf[ks][0] = p0[0]; qf[ks][1] = p1[0];
        qf[ks][2] = p0[4]; qf[ks][3] = p1[4];
    }

    float oa[16][4];
#pragma unroll
    for (int nf = 0; nf < 16; nf++)
#pragma unroll
        for (int r = 0; r < 4; r++) oa[nf][r] = 0.0f;
    float m0 = -1e30f, m1 = -1e30f, l0 = 0.0f, l1 = 0.0f;

    auto load_kv = [&](int kt) {
        const int s = kt & 1;
        const int kv0 = kt * FKV;
        const uint32_t kdst = sb + (uint32_t)(s * STG) * 4;
        const uint32_t vdst = sb + (uint32_t)(s * STG + KST) * 4;
#pragma unroll
        for (int i = 0; i < 8; i++) {
            const int c   = tid + i * 256;   // 0..2047
            const int row = c >> 5;          // 0..63
            const int col = (c & 31) * 4;    // float index 0..124
            cp16(kdst + (uint32_t)(row * KSTR + col) * 4,
                 kbase + (size_t)(kv0 + row) * DH + col);
            cp16(vdst + (uint32_t)(row * VSTR + col) * 4,
                 vbase + (size_t)(kv0 + row) * DH + col);
        }
        CP_COMMIT();
    };

    load_kv(0);

    for (int kt = 0; kt < ntiles; kt++) {
        const int s = kt & 1;
        if (kt + 1 < ntiles) { load_kv(kt + 1); cp_wait<1>(); }
        else                 { cp_wait<0>(); }
        __syncthreads();

        const float* Ks = sm + s * STG;
        const float* Vs = sm + s * STG + KST;
        float* Pw = sm + P_OFF + (w * 16) * PSTR;   // warp-private P rows

        // ---- S = Q K^T ----
        float sf[8][4];
#pragma unroll
        for (int nf = 0; nf < 8; nf++)
#pragma unroll
            for (int r = 0; r < 4; r++) sf[nf][r] = 0.0f;

#pragma unroll
        for (int ks = 0; ks < 16; ks++) {
            const uint32_t a0 = __float_as_uint(qf[ks][0]);
            const uint32_t a1 = __float_as_uint(qf[ks][1]);
            const uint32_t a2 = __float_as_uint(qf[ks][2]);
            const uint32_t a3 = __float_as_uint(qf[ks][3]);
#pragma unroll
            for (int nf = 0; nf < 8; nf++) {
                const float* kp = Ks + (nf * 8 + qr) * KSTR + ks * 8 + qc;
                mma_tf32_16n8k8(sf[nf][0], sf[nf][1], sf[nf][2], sf[nf][3],
                                a0, a1, a2, a3,
                                __float_as_uint(kp[0]),
                                __float_as_uint(kp[4]));
            }
        }

        // ---- scale + causal mask + row max ----
        const int kv0 = kt * FKV;
        const bool dm = (kt >= ntiles - 2);
        float rm0 = -1e30f, rm1 = -1e30f;
#pragma unroll
        for (int nf = 0; nf < 8; nf++) {
            float v0 = sf[nf][0] * scale, v1 = sf[nf][1] * scale;
            float v2 = sf[nf][2] * scale, v3 = sf[nf][3] * scale;
            if (dm) {
                const int cg = kv0 + nf * 8 + 2 * qc;
                if (cg     > r0g)     v0 = -1e30f;
                if (cg + 1 > r0g)     v1 = -1e30f;
                if (cg     > r0g + 8) v2 = -1e30f;
                if (cg + 1 > r0g + 8) v3 = -1e30f;
            }
            sf[nf][0] = v0; sf[nf][1] = v1; sf[nf][2] = v2; sf[nf][3] = v3;
            rm0 = fmaxf(rm0, fmaxf(v0, v1));
            rm1 = fmaxf(rm1, fmaxf(v2, v3));
        }
        rm0 = fmaxf(rm0, __shfl_xor_sync(0xffffffffu, rm0, 1));
        rm0 = fmaxf(rm0, __shfl_xor_sync(0xffffffffu, rm0, 2));
        rm1 = fmaxf(rm1, __shfl_xor_sync(0xffffffffu, rm1, 1));
        rm1 = fmaxf(rm1, __shfl_xor_sync(0xffffffffu, rm1, 2));

        const float mn0 = fmaxf(m0, rm0), mn1 = fmaxf(m1, rm1);
        const float sc0 = __expf(m0 - mn0), sc1 = __expf(m1 - mn1);
        m0 = mn0; m1 = mn1;

        // ---- P = exp(S - m), row sums, store tf32 P to smem ----
        float rs0 = 0.0f, rs1 = 0.0f;
#pragma unroll
        for (int nf = 0; nf < 8; nf++) {
            const float p0 = __expf(sf[nf][0] - mn0);
            const float p1 = __expf(sf[nf][1] - mn0);
            const float p2 = __expf(sf[nf][2] - mn1);
            const float p3 = __expf(sf[nf][3] - mn1);
            rs0 += p0 + p1; rs1 += p2 + p3;
            float2 lo, hi;
            lo.x = rna_tf32(p0); lo.y = rna_tf32(p1);
            hi.x = rna_tf32(p2); hi.y = rna_tf32(p3);
            *(float2*)&Pw[qr * PSTR + nf * 8 + 2 * qc]       = lo;
            *(float2*)&Pw[(qr + 8) * PSTR + nf * 8 + 2 * qc] = hi;
        }
        rs0 += __shfl_xor_sync(0xffffffffu, rs0, 1);
        rs0 += __shfl_xor_sync(0xffffffffu, rs0, 2);
        rs1 += __shfl_xor_sync(0xffffffffu, rs1, 1);
        rs1 += __shfl_xor_sync(0xffffffffu, rs1, 2);
        l0 = l0 * sc0 + rs0;
        l1 = l1 * sc1 + rs1;

        // ---- rescale O ----
#pragma unroll
        for (int nf = 0; nf < 16; nf++) {
            oa[nf][0] *= sc0; oa[nf][1] *= sc0;
            oa[nf][2] *= sc1; oa[nf][3] *= sc1;
        }
        __syncwarp();

        // ---- O += P V ----
#pragma unroll
        for (int kb = 0; kb < 8; kb++) {
            const float* pp = Pw + qr * PSTR + kb * 8 + qc;
            const uint32_t a0 = __float_as_uint(pp[0]);
            const uint32_t a1 = __float_as_uint(pp[8 * PSTR]);
            const uint32_t a2 = __float_as_uint(pp[4]);
            const uint32_t a3 = __float_as_uint(pp[8 * PSTR + 4]);
#pragma unroll
            for (int nf = 0; nf < 16; nf++) {
                const float* vp = Vs + (kb * 8 + qc) * VSTR + nf * 8 + qr;
                mma_tf32_16n8k8(oa[nf][0], oa[nf][1], oa[nf][2], oa[nf][3],
                                a0, a1, a2, a3,
                                __float_as_uint(vp[0]),
                                __float_as_uint(vp[4 * VSTR]));
            }
        }
        __syncthreads();
    }

    // ---- epilogue: normalize, round to tf32, store ----
    const float inv0 = 1.0f / l0, inv1 = 1.0f / l1;
    float* ob = gout + head_off;
#pragma unroll
    for (int nf = 0; nf < 16; nf++) {
        const int col = nf * 8 + 2 * qc;
        float2 v0, v1;
        v0.x = rna_tf32(oa[nf][0] * inv0); v0.y = rna_tf32(oa[nf][1] * inv0);
        v1.x = rna_tf32(oa[nf][2] * inv1); v1.y = rna_tf32(oa[nf][3] * inv1);
        *(float2*)&ob[(size_t)r0g * DH + col]       = v0;
        *(float2*)&ob[(size_t)(r0g + 8) * DH + col] = v1;
    }
}

// ---------------------------------------------------------------------------
extern "C" void kernel_launch(void* const* d_in, const int* in_sizes, int n_in,
                              void* d_out, int out_size)
{
    const float* src = (const float*)d_in[0];
    const float* Wq  = (const float*)d_in[1];
    const float* bq  = (const float*)d_in[2];
    const float* Wk  = (const float*)d_in[3];
    const float* bk  = (const float*)d_in[4];
    const float* Wv  = (const float*)d_in[5];
    const float* bv  = (const float*)d_in[6];
    const float* Wo  = (const float*)d_in[7];
    const float* bo  = (const float*)d_in[8];
    float* out = (float*)d_out;

    float *q, *k, *v, *o, *a, *wt;
    cudaGetSymbolAddress((void**)&q,  g_q);
    cudaGetSymbolAddress((void**)&k,  g_k);
    cudaGetSymbolAddress((void**)&v,  g_v);
    cudaGetSymbolAddress((void**)&o,  g_o);
    cudaGetSymbolAddress((void**)&a,  g_a);
    cudaGetSymbolAddress((void**)&wt, g_wt);

    cudaFuncSetAttribute(flash2_kernel,
                         cudaFuncAttributeMaxDynamicSharedMemorySize,
                         FLASH2_SMEM);
    cudaFuncSetAttribute(tc_gemm<false, true, true>,
                         cudaFuncAttributeMaxDynamicSharedMemorySize, GEMM_SMEM);
    cudaFuncSetAttribute(tc_gemm<true, false, false>,
                         cudaFuncAttributeMaxDynamicSharedMemorySize, GEMM_SMEM);

    const dim3 ggrid(NDIM / 128, MROWS / 128);   // (16, 32)
    const int NW4 = KDIM * NDIM / 4;

    // Round activations once.
    round_tf32_kernel<<<1024, 256>>>((const float4*)src, (float4*)a,
                                     MROWS * KDIM / 4);

    // Q/K/V projections on HMMA tf32 (epilogue rounds outputs to tf32).
    round_tf32_kernel<<<1024, 256>>>((const float4*)Wq, (float4*)wt, NW4);
    tc_gemm<false, true, true><<<ggrid, 256, GEMM_SMEM>>>(a, wt, bq, q);
    round_tf32_kernel<<<1024, 256>>>((const float4*)Wk, (float4*)wt, NW4);
    tc_gemm<false, true, true><<<ggrid, 256, GEMM_SMEM>>>(a, wt, bk, k);
    round_tf32_kernel<<<1024, 256>>>((const float4*)Wv, (float4*)wt, NW4);
    tc_gemm<false, true, true><<<ggrid, 256, GEMM_SMEM>>>(a, wt, bv, v);

    // Attention on HMMA tf32 (epilogue rounds output to tf32).
    flash2_kernel<<<dim3(T / FQ, NH, BSZ), 256, FLASH2_SMEM>>>(q, k, v, o);

    // O projection (gathers heads layout; full-precision fp32 output).
    round_tf32_kernel<<<1024, 256>>>((const float4*)Wo, (float4*)wt, NW4);
    tc_gemm<true, false, false><<<ggrid, 256, GEMM_SMEM>>>(o, wt, bo, out);
}

// round 7
// speedup vs baseline: 4.5883x; 1.0507x over previous
#include <cuda_runtime.h>
#include <math.h>
#include <stdint.h>

// Problem constants
#define BSZ 2
#define T   2048
#define C   2048
#define NH  16
#define DH  128
#define MROWS (BSZ * T)      // 4096
#define KDIM  C              // 2048
#define NDIM  C              // 2048

// Scratch
__device__ float g_q[BSZ * NH * T * DH];
__device__ float g_k[BSZ * NH * T * DH];
__device__ float g_v[BSZ * NH * T * DH];
__device__ float g_o[BSZ * NH * T * DH];
__device__ float g_a[MROWS * KDIM];       // tf32-rounded src
__device__ float g_w0[KDIM * NDIM];       // rounded Wq
__device__ float g_w1[KDIM * NDIM];       // rounded Wk
__device__ float g_w2[KDIM * NDIM];       // rounded Wv
__device__ float g_w3[KDIM * NDIM];       // rounded Wo

// ---------------------------------------------------------------------------
// PTX helpers (compute_103-safe: mma.sync + cp.async only)
// ---------------------------------------------------------------------------
__device__ __forceinline__ uint32_t smem_u32(const void* p) {
    uint32_t a;
    asm("{ .reg .u64 t; cvta.to.shared.u64 t, %1; cvt.u32.u64 %0, t; }"
        : "=r"(a) : "l"(p));
    return a;
}

__device__ __forceinline__ float rna_tf32(float x) {
    uint32_t r;
    asm("cvt.rna.tf32.f32 %0, %1;" : "=r"(r) : "f"(x));
    return __uint_as_float(r);
}

__device__ __forceinline__ float fast_exp2(float x) {
    float y;
    asm("ex2.approx.f32 %0, %1;" : "=f"(y) : "f"(x));
    return y;
}

__device__ __forceinline__ void cp16(uint32_t dst, const float* src) {
    asm volatile("cp.async.cg.shared.global [%0], [%1], 16;"
                 :: "r"(dst), "l"(src));
}
#define CP_COMMIT() asm volatile("cp.async.commit_group;" ::: "memory")
template <int N>
__device__ __forceinline__ void cp_wait() {
    asm volatile("cp.async.wait_group %0;" :: "n"(N) : "memory");
}

__device__ __forceinline__ void mma_tf32_16n8k8(
    float& d0, float& d1, float& d2, float& d3,
    uint32_t a0, uint32_t a1, uint32_t a2, uint32_t a3,
    uint32_t b0, uint32_t b1)
{
    asm volatile(
        "mma.sync.aligned.m16n8k8.row.col.f32.tf32.tf32.f32 "
        "{%0,%1,%2,%3}, {%4,%5,%6,%7}, {%8,%9}, {%0,%1,%2,%3};\n"
        : "+f"(d0), "+f"(d1), "+f"(d2), "+f"(d3)
        : "r"(a0), "r"(a1), "r"(a2), "r"(a3), "r"(b0), "r"(b1));
}

// ---------------------------------------------------------------------------
// Fused rounding pre-pass: src + 4 weights in one launch (gridDim.y selects)
// ---------------------------------------------------------------------------
struct RoundArgs {
    const float4* in[5];
    float4*       out[5];
    int           n4[5];
};

__global__ void round_all_kernel(RoundArgs ra) {
    const int y = blockIdx.y;
    const float4* in  = ra.in[y];
    float4*       out = ra.out[y];
    const int n4 = ra.n4[y];
    int i = blockIdx.x * blockDim.x + threadIdx.x;
    const int stride = gridDim.x * blockDim.x;
    for (; i < n4; i += stride) {
        float4 v = in[i];
        v.x = rna_tf32(v.x); v.y = rna_tf32(v.y);
        v.z = rna_tf32(v.z); v.w = rna_tf32(v.w);
        out[i] = v;
    }
}

// ---------------------------------------------------------------------------
// HMMA tf32 GEMM body: out[M=4096, N=2048] = A[M,K=2048] @ W[K,N] + bias
// 128x128 block tile, K-slab 32, 3-stage cp.async pipeline, 256 threads,
// 8 warps (2x4), warp tile 64x32, mma.sync m16n8k8 tf32.
//   GATHER_A:    A read from heads layout [B,N,T,D]
//   SCATTER_OUT: out written to heads layout [B,N,T,D]
//   ROUND_OUT:   RNA-round the stored result to tf32
// ---------------------------------------------------------------------------
#define BK 32
#define NKS (KDIM / BK)          // 64
#define STAGES 3
#define AS_STRIDE 36
#define BS_STRIDE 136
#define A_ST_FLOATS (128 * AS_STRIDE)            // 4608
#define B_ST_FLOATS (BK * BS_STRIDE)             // 4352
#define ST_FLOATS (A_ST_FLOATS + B_ST_FLOATS)    // 8960
#define GEMM_SMEM (STAGES * ST_FLOATS * 4)       // 107520 bytes

template <bool GATHER_A, bool SCATTER_OUT, bool ROUND_OUT>
__device__ void gemm_body(
    const float* __restrict__ A, const float* __restrict__ W,
    const float* __restrict__ bias, float* __restrict__ out,
    int m_base, int n_base)
{
    extern __shared__ float smf[];
    const uint32_t sb = smem_u32(smf);
    const int tid  = threadIdx.x;
    const int lane = tid & 31;
    const int w    = tid >> 5;
    const int wm   = (w >> 2) * 64;    // warp m offset (0 or 64)
    const int wn   = (w & 3) * 32;     // warp n offset (0..96)

    // ---- load geometry: 4 granules (16B) per operand per slab per thread ----
    uint32_t a_off[4], b_off[4];
    const float* a_fix[4];
    const float* b_fix[4];
#pragma unroll
    for (int i = 0; i < 4; i++) {
        const int g  = tid + i * 256;
        const int ar = g >> 3;          // 0..127  (m row)
        const int ac = g & 7;           // 16B chunk in 128B k-row
        a_off[i] = (uint32_t)(ar * AS_STRIDE + ac * 4) * 4;
        if (GATHER_A) {
            const int m = m_base + ar;
            a_fix[i] = A + (size_t)(m >> 11) * (NH * T * DH)
                         + (size_t)(m & 2047) * DH + ac * 4;
        } else {
            a_fix[i] = A + (size_t)(m_base + ar) * KDIM + ac * 4;
        }
        const int br = g >> 5;          // 0..31  (k row)
        const int bc = g & 31;          // 16B chunk in 512B n-row
        b_off[i] = (uint32_t)(A_ST_FLOATS + br * BS_STRIDE + bc * 4) * 4;
        b_fix[i] = W + (size_t)br * NDIM + n_base + bc * 4;
    }

    auto load_slab = [&](int ks) {
        const int s = ks % STAGES;
        const uint32_t stage = sb + (uint32_t)(s * ST_FLOATS) * 4;
        const int k0 = ks * BK;
#pragma unroll
        for (int i = 0; i < 4; i++) {
            const float* asrc;
            if (GATHER_A)
                asrc = a_fix[i] + (size_t)(k0 >> 7) * (T * DH) + (k0 & 127);
            else
                asrc = a_fix[i] + k0;
            cp16(stage + a_off[i], asrc);
            cp16(stage + b_off[i], b_fix[i] + (size_t)k0 * NDIM);
        }
        CP_COMMIT();
    };

    float acc[4][4][4];   // [mf][nf][reg]
#pragma unroll
    for (int mf = 0; mf < 4; mf++)
#pragma unroll
        for (int nf = 0; nf < 4; nf++)
#pragma unroll
            for (int r = 0; r < 4; r++) acc[mf][nf][r] = 0.0f;

    load_slab(0);
    load_slab(1);

    const int qr = lane >> 2;   // 0..7
    const int qc = lane & 3;    // 0..3

    for (int ks = 0; ks < NKS; ks++) {
        if (ks >= NKS - 1) cp_wait<0>(); else cp_wait<1>();
        __syncthreads();
        // Safe: this barrier proves all warps finished slab ks-1, whose
        // buffer (== buffer of ks+2 in the 3-stage ring) we now overwrite.
        if (ks + 2 < NKS) load_slab(ks + 2);

        const float* st = smf + (ks % STAGES) * ST_FLOATS;
        const float* As = st;                       // [128][36]
        const float* Bs = st + A_ST_FLOATS;         // [32][136]

#pragma unroll
        for (int kk = 0; kk < 4; kk++) {
            const int kb = kk * 8;
            uint32_t bfr[4][2];
#pragma unroll
            for (int nf = 0; nf < 4; nf++) {
                const int cn = wn + nf * 8 + qr;
                bfr[nf][0] = __float_as_uint(Bs[(kb + qc)     * BS_STRIDE + cn]);
                bfr[nf][1] = __float_as_uint(Bs[(kb + qc + 4) * BS_STRIDE + cn]);
            }
#pragma unroll
            for (int mf = 0; mf < 4; mf++) {
                const int r0 = wm + mf * 16 + qr;
                const uint32_t a0 = __float_as_uint(As[r0      * AS_STRIDE + kb + qc]);
                const uint32_t a1 = __float_as_uint(As[(r0 + 8)* AS_STRIDE + kb + qc]);
                const uint32_t a2 = __float_as_uint(As[r0      * AS_STRIDE + kb + qc + 4]);
                const uint32_t a3 = __float_as_uint(As[(r0 + 8)* AS_STRIDE + kb + qc + 4]);
#pragma unroll
                for (int nf = 0; nf < 4; nf++)
                    mma_tf32_16n8k8(acc[mf][nf][0], acc[mf][nf][1],
                                    acc[mf][nf][2], acc[mf][nf][3],
                                    a0, a1, a2, a3, bfr[nf][0], bfr[nf][1]);
            }
        }
    }

    // ---- epilogue: bias + store (optionally scatter / round) ----
#pragma unroll
    for (int mf = 0; mf < 4; mf++) {
        const int row0 = m_base + wm + mf * 16 + qr;
#pragma unroll
        for (int nf = 0; nf < 4; nf++) {
            const int col = n_base + wn + nf * 8 + 2 * qc;
            const float bx = bias[col];
            const float by = bias[col + 1];
#pragma unroll
            for (int half = 0; half < 2; half++) {
                const int row = row0 + half * 8;
                float2 v;
                v.x = acc[mf][nf][half * 2 + 0] + bx;
                v.y = acc[mf][nf][half * 2 + 1] + by;
                if (ROUND_OUT) { v.x = rna_tf32(v.x); v.y = rna_tf32(v.y); }
                if (SCATTER_OUT) {
                    const int b = row >> 11, t = row & 2047;
                    const int h = col >> 7,  d = col & 127;
                    *(float2*)&out[(((size_t)b * NH + h) * T + t) * DH + d] = v;
                } else {
                    *(float2*)&out[(size_t)row * NDIM + col] = v;
                }
            }
        }
    }
}

// Fused Q/K/V projection: blockIdx.z selects weight/bias/output.
__global__ __launch_bounds__(256, 2) void qkv_gemm_kernel(
    const float* __restrict__ A,
    const float* __restrict__ w0, const float* __restrict__ w1,
    const float* __restrict__ w2,
    const float* __restrict__ b0, const float* __restrict__ b1,
    const float* __restrict__ b2,
    float* __restrict__ o0, float* __restrict__ o1, float* __restrict__ o2)
{
    const int z = blockIdx.z;
    const float* W    = (z == 0) ? w0 : (z == 1) ? w1 : w2;
    const float* bias = (z == 0) ? b0 : (z == 1) ? b1 : b2;
    float*       out  = (z == 0) ? o0 : (z == 1) ? o1 : o2;
    gemm_body<false, true, true>(A, W, bias, out,
                                 blockIdx.y * 128, blockIdx.x * 128);
}

// O projection (gathers heads layout, fp32 output).
__global__ __launch_bounds__(256, 2) void o_gemm_kernel(
    const float* __restrict__ A, const float* __restrict__ W,
    const float* __restrict__ bias, float* __restrict__ out)
{
    gemm_body<true, false, false>(A, W, bias, out,
                                  blockIdx.y * 128, blockIdx.x * 128);
}

// ---------------------------------------------------------------------------
// Tensor-core flash attention (causal). BQ=128, BKV=64, D=128, 256 threads,
// 8 warps x 16 q-rows. tf32 mma for QK^T and PV; fp32 online softmax in
// registers (base-2 domain, log2e folded into scale), quad shfl reductions.
// Double-buffered cp.async K/V tiles; ONE barrier per kv tile.
// smem (floats): K[2][64][132], V[2][64][136], P[128][68]
// ---------------------------------------------------------------------------
#define FQ 128
#define FKV 64
#define KSTR 132
#define VSTR 136
#define PSTR 68
#define KST (FKV * KSTR)                 // 8448
#define VST (FKV * VSTR)                 // 8704
#define STG (KST + VST)                  // 17152
#define P_OFF (2 * STG)                  // 34304
#define FLASH2_SMEM ((P_OFF + FQ * PSTR) * 4)   // 172032 bytes

__global__ __launch_bounds__(256) void flash2_kernel(
    const float* __restrict__ gq, const float* __restrict__ gk,
    const float* __restrict__ gv, float* __restrict__ gout)
{
    extern __shared__ float sm[];
    const uint32_t sb = smem_u32(sm);
    const int tid  = threadIdx.x;
    const int lane = tid & 31;
    const int w    = tid >> 5;
    const int qr   = lane >> 2;
    const int qc   = lane & 3;

    const int qt = (int)gridDim.x - 1 - (int)blockIdx.x;  // heavy tiles first
    const int h  = blockIdx.y;
    const int b  = blockIdx.z;
    const int q0 = qt * FQ;
    const size_t head_off = ((size_t)b * NH + h) * T * DH;
    const float* qbase = gq + head_off;
    const float* kbase = gk + head_off;
    const float* vbase = gv + head_off;

    const int ntiles = 2 * qt + 2;
    // 1/sqrt(128) * log2(e): softmax computed in base-2 domain.
    const float scale = 0.08838834764831845f * 1.4426950408889634f;

    // ---- Q fragments (held in registers for whole kernel) ----
    const int r0g = q0 + w * 16 + qr;
    float qf[16][4];
#pragma unroll
    for (int ks = 0; ks < 16; ks++) {
        const float* p0 = qbase + (size_t)r0g * DH + ks * 8 + qc;
        const float* p1 = qbase + (size_t)(r0g + 8) * DH + ks * 8 + qc;
        qf[ks][0] = p0[0]; qf[ks][1] = p1[0];
        qf[ks][2] = p0[4]; qf[ks][3] = p1[4];
    }

    float oa[16][4];
#pragma unroll
    for (int nf = 0; nf < 16; nf++)
#pragma unroll
        for (int r = 0; r < 4; r++) oa[nf][r] = 0.0f;
    float m0 = -1e30f, m1 = -1e30f, l0 = 0.0f, l1 = 0.0f;

    auto load_kv = [&](int kt) {
        const int s = kt & 1;
        const int kv0 = kt * FKV;
        const uint32_t kdst = sb + (uint32_t)(s * STG) * 4;
        const uint32_t vdst = sb + (uint32_t)(s * STG + KST) * 4;
#pragma unroll
        for (int i = 0; i < 8; i++) {
            const int c   = tid + i * 256;   // 0..2047
            const int row = c >> 5;          // 0..63
            const int col = (c & 31) * 4;    // float index 0..124
            cp16(kdst + (uint32_t)(row * KSTR + col) * 4,
                 kbase + (size_t)(kv0 + row) * DH + col);
            cp16(vdst + (uint32_t)(row * VSTR + col) * 4,
                 vbase + (size_t)(kv0 + row) * DH + col);
        }
        CP_COMMIT();
    };

    load_kv(0);

    for (int kt = 0; kt < ntiles; kt++) {
        const int s = kt & 1;
        cp_wait<0>();
        __syncthreads();
        // Barrier above proves all warps are done with buffer (kt-1)&1
        // == (kt+1)&1, so the prefetch below is race-free.
        if (kt + 1 < ntiles) load_kv(kt + 1);

        const float* Ks = sm + s * STG;
        const float* Vs = sm + s * STG + KST;
        float* Pw = sm + P_OFF + (w * 16) * PSTR;   // warp-private P rows

        // ---- S = Q K^T ----
        float sf[8][4];
#pragma unroll
        for (int nf = 0; nf < 8; nf++)
#pragma unroll
            for (int r = 0; r < 4; r++) sf[nf][r] = 0.0f;

#pragma unroll
        for (int ks = 0; ks < 16; ks++) {
            const uint32_t a0 = __float_as_uint(qf[ks][0]);
            const uint32_t a1 = __float_as_uint(qf[ks][1]);
            const uint32_t a2 = __float_as_uint(qf[ks][2]);
            const uint32_t a3 = __float_as_uint(qf[ks][3]);
#pragma unroll
            for (int nf = 0; nf < 8; nf++) {
                const float* kp = Ks + (nf * 8 + qr) * KSTR + ks * 8 + qc;
                mma_tf32_16n8k8(sf[nf][0], sf[nf][1], sf[nf][2], sf[nf][3],
                                a0, a1, a2, a3,
                                __float_as_uint(kp[0]),
                                __float_as_uint(kp[4]));
            }
        }

        // ---- scale (base-2) + causal mask + row max ----
        const int kv0 = kt * FKV;
        const bool dm = (kt >= ntiles - 2);
        float rm0 = -1e30f, rm1 = -1e30f;
#pragma unroll
        for (int nf = 0; nf < 8; nf++) {
            float v0 = sf[nf][0] * scale, v1 = sf[nf][1] * scale;
            float v2 = sf[nf][2] * scale, v3 = sf[nf][3] * scale;
            if (dm) {
                const int cg = kv0 + nf * 8 + 2 * qc;
                if (cg     > r0g)     v0 = -1e30f;
                if (cg + 1 > r0g)     v1 = -1e30f;
                if (cg     > r0g + 8) v2 = -1e30f;
                if (cg + 1 > r0g + 8) v3 = -1e30f;
            }
            sf[nf][0] = v0; sf[nf][1] = v1; sf[nf][2] = v2; sf[nf][3] = v3;
            rm0 = fmaxf(rm0, fmaxf(v0, v1));
            rm1 = fmaxf(rm1, fmaxf(v2, v3));
        }
        rm0 = fmaxf(rm0, __shfl_xor_sync(0xffffffffu, rm0, 1));
        rm0 = fmaxf(rm0, __shfl_xor_sync(0xffffffffu, rm0, 2));
        rm1 = fmaxf(rm1, __shfl_xor_sync(0xffffffffu, rm1, 1));
        rm1 = fmaxf(rm1, __shfl_xor_sync(0xffffffffu, rm1, 2));

        const float mn0 = fmaxf(m0, rm0), mn1 = fmaxf(m1, rm1);
        const float sc0 = fast_exp2(m0 - mn0), sc1 = fast_exp2(m1 - mn1);
        m0 = mn0; m1 = mn1;

        // ---- P = exp2(S - m), row sums, store tf32 P to smem ----
        float rs0 = 0.0f, rs1 = 0.0f;
#pragma unroll
        for (int nf = 0; nf < 8; nf++) {
            const float p0 = fast_exp2(sf[nf][0] - mn0);
            const float p1 = fast_exp2(sf[nf][1] - mn0);
            const float p2 = fast_exp2(sf[nf][2] - mn1);
            const float p3 = fast_exp2(sf[nf][3] - mn1);
            rs0 += p0 + p1; rs1 += p2 + p3;
            float2 lo, hi;
            lo.x = rna_tf32(p0); lo.y = rna_tf32(p1);
            hi.x = rna_tf32(p2); hi.y = rna_tf32(p3);
            *(float2*)&Pw[qr * PSTR + nf * 8 + 2 * qc]       = lo;
            *(float2*)&Pw[(qr + 8) * PSTR + nf * 8 + 2 * qc] = hi;
        }
        rs0 += __shfl_xor_sync(0xffffffffu, rs0, 1);
        rs0 += __shfl_xor_sync(0xffffffffu, rs0, 2);
        rs1 += __shfl_xor_sync(0xffffffffu, rs1, 1);
        rs1 += __shfl_xor_sync(0xffffffffu, rs1, 2);
        l0 = l0 * sc0 + rs0;
        l1 = l1 * sc1 + rs1;

        // ---- rescale O ----
#pragma unroll
        for (int nf = 0; nf < 16; nf++) {
            oa[nf][0] *= sc0; oa[nf][1] *= sc0;
            oa[nf][2] *= sc1; oa[nf][3] *= sc1;
        }
        __syncwarp();

        // ---- O += P V ----
#pragma unroll
        for (int kb = 0; kb < 8; kb++) {
            const float* pp = Pw + qr * PSTR + kb * 8 + qc;
            const uint32_t a0 = __float_as_uint(pp[0]);
            const uint32_t a1 = __float_as_uint(pp[8 * PSTR]);
            const uint32_t a2 = __float_as_uint(pp[4]);
            const uint32_t a3 = __float_as_uint(pp[8 * PSTR + 4]);
#pragma unroll
            for (int nf = 0; nf < 16; nf++) {
                const float* vp = Vs + (kb * 8 + qc) * VSTR + nf * 8 + qr;
                mma_tf32_16n8k8(oa[nf][0], oa[nf][1], oa[nf][2], oa[nf][3],
                                a0, a1, a2, a3,
                                __float_as_uint(vp[0]),
                                __float_as_uint(vp[4 * VSTR]));
            }
        }
    }

    // ---- epilogue: normalize, round to tf32, store ----
    const float inv0 = 1.0f / l0, inv1 = 1.0f / l1;
    float* ob = gout + head_off;
#pragma unroll
    for (int nf = 0; nf < 16; nf++) {
        const int col = nf * 8 + 2 * qc;
        float2 v0, v1;
        v0.x = rna_tf32(oa[nf][0] * inv0); v0.y = rna_tf32(oa[nf][1] * inv0);
        v1.x = rna_tf32(oa[nf][2] * inv1); v1.y = rna_tf32(oa[nf][3] * inv1);
        *(float2*)&ob[(size_t)r0g * DH + col]       = v0;
        *(float2*)&ob[(size_t)(r0g + 8) * DH + col] = v1;
    }
}

// ---------------------------------------------------------------------------
extern "C" void kernel_launch(void* const* d_in, const int* in_sizes, int n_in,
                              void* d_out, int out_size)
{
    const float* src = (const float*)d_in[0];
    const float* Wq  = (const float*)d_in[1];
    const float* bq  = (const float*)d_in[2];
    const float* Wk  = (const float*)d_in[3];
    const float* bk  = (const float*)d_in[4];
    const float* Wv  = (const float*)d_in[5];
    const float* bv  = (const float*)d_in[6];
    const float* Wo  = (const float*)d_in[7];
    const float* bo  = (const float*)d_in[8];
    float* out = (float*)d_out;

    float *q, *k, *v, *o, *a, *w0, *w1, *w2, *w3;
    cudaGetSymbolAddress((void**)&q,  g_q);
    cudaGetSymbolAddress((void**)&k,  g_k);
    cudaGetSymbolAddress((void**)&v,  g_v);
    cudaGetSymbolAddress((void**)&o,  g_o);
    cudaGetSymbolAddress((void**)&a,  g_a);
    cudaGetSymbolAddress((void**)&w0, g_w0);
    cudaGetSymbolAddress((void**)&w1, g_w1);
    cudaGetSymbolAddress((void**)&w2, g_w2);
    cudaGetSymbolAddress((void**)&w3, g_w3);

    cudaFuncSetAttribute(flash2_kernel,
                         cudaFuncAttributeMaxDynamicSharedMemorySize,
                         FLASH2_SMEM);
    cudaFuncSetAttribute(qkv_gemm_kernel,
                         cudaFuncAttributeMaxDynamicSharedMemorySize, GEMM_SMEM);
    cudaFuncSetAttribute(o_gemm_kernel,
                         cudaFuncAttributeMaxDynamicSharedMemorySize, GEMM_SMEM);

    // 1. One fused tf32-rounding pass: src + Wq/Wk/Wv/Wo.
    RoundArgs ra;
    ra.in[0] = (const float4*)src; ra.out[0] = (float4*)a;
    ra.n4[0] = MROWS * KDIM / 4;
    ra.in[1] = (const float4*)Wq;  ra.out[1] = (float4*)w0;
    ra.in[2] = (const float4*)Wk;  ra.out[2] = (float4*)w1;
    ra.in[3] = (const float4*)Wv;  ra.out[3] = (float4*)w2;
    ra.in[4] = (const float4*)Wo;  ra.out[4] = (float4*)w3;
    ra.n4[1] = ra.n4[2] = ra.n4[3] = ra.n4[4] = KDIM * NDIM / 4;
    round_all_kernel<<<dim3(1024, 5), 256>>>(ra);

    // 2. Fused Q/K/V projections (one launch, z selects).
    qkv_gemm_kernel<<<dim3(NDIM / 128, MROWS / 128, 3), 256, GEMM_SMEM>>>(
        a, w0, w1, w2, bq, bk, bv, q, k, v);

    // 3. Attention on HMMA tf32.
    flash2_kernel<<<dim3(T / FQ, NH, BSZ), 256, FLASH2_SMEM>>>(q, k, v, o);

    // 4. O projection (gathers heads layout; fp32 output).
    o_gemm_kernel<<<dim3(NDIM / 128, MROWS / 128), 256, GEMM_SMEM>>>(
        o, w3, bo, out);
}